// round 13
// baseline (speedup 1.0000x reference)
#include <cuda_runtime.h>
#include <cstdint>

// Fully fused quantized CIFAR-10 net. Depthwise via dp4a, pw2/pw3 via IMMA
// mma.m16n8k32.s8 with register-resident pooling; bank-conflict-free swizzles.
// 192 threads x 7 CTAs/SM: whole 1024-CTA grid resident in ONE wave (148*7=1036).
// PDL overlaps prep with conv0..pw1. Integer round-half-even ==> bit-exact.

#define PTHREADS 256   // prep kernel
#define QT 192         // qnet threads per CTA

// ---------------- packed weight globals (written by prep_kernel) ----------------
__device__ __align__(16) uint32_t gPW2[512];   // pw2 [oc*8+g]: 4 ic codes
__device__ __align__(16) uint32_t gPW3[2048];  // pw3 [oc*16+g]: 4 ic codes
__device__ uint32_t gFC1[8192];  // fc1 [g*256+oc]: 4 ic codes (coalesced by oc)
__device__ uint32_t gFC2[640];   // fc2 [oc*64+g]: 4 ic codes
__device__ uint32_t gDW2r[96];   // dw2 row-packed [c*3+ky]
__device__ uint32_t gDW3r[192];  // dw3 row-packed [c*3+ky]

// ---------------- helpers ----------------
__device__ __forceinline__ int clampi(int v, int lo, int hi) { return min(max(v, lo), hi); }
__device__ __forceinline__ uint32_t pack4(int a, int b, int c, int d) {
    return (uint32_t)(a & 0xFF) | ((uint32_t)(b & 0xFF) << 8) |
           ((uint32_t)(c & 0xFF) << 16) | ((uint32_t)(d & 0xFF) << 24);
}
__device__ __forceinline__ int qw4c(float w) {
    float q = rintf(w * 4.f); return (int)fmaxf(-8.f, fminf(7.f, q));
}
__device__ __forceinline__ int qw8c(float w) {
    float q = rintf(w * 4.f); return (int)fmaxf(-128.f, fminf(127.f, q));
}
__device__ __forceinline__ int qa8c(float v) {
    return clampi(__float2int_rn(v * 16.f), -128, 127);
}
// branch-free round-half-even of S/4
__device__ __forceinline__ int rq2(int S) {
    return (S + 1 + ((S >> 2) & 1)) >> 2;
}
// branch-free round-half-even of S/32
__device__ __forceinline__ int rq5(int S) {
    return (S + 15 + ((S >> 5) & 1)) >> 5;
}
// fused QuantReLU4 + S_ACT4 requant
__device__ __forceinline__ int fq4(int S) {
    int m = max(S, 0);
    return min((m + 1 + ((m >> 2) & 1)) >> 2, 7);
}
// packed fq4 on 4 unsigned bytes (values in [0,252])
__device__ __forceinline__ uint32_t fq4x4(uint32_t p) {
    uint32_t inc = ((p >> 2) & 0x01010101u) + 0x01010101u;
    uint32_t t = __vadd4(p, inc);
    return __vminu4((t >> 2) & 0x3F3F3F3Fu, 0x07070707u);
}
// s8 tensor-core mma, D += A*B (s32 accumulate)
__device__ __forceinline__ void mma_s8(int& d0, int& d1, int& d2, int& d3,
                                       int a0, int a1, int a2, int a3,
                                       int b0, int b1) {
    asm volatile("mma.sync.aligned.m16n8k32.row.col.s32.s8.s8.s32 "
                 "{%0,%1,%2,%3}, {%4,%5,%6,%7}, {%8,%9}, {%0,%1,%2,%3};"
                 : "+r"(d0), "+r"(d1), "+r"(d2), "+r"(d3)
                 : "r"(a0), "r"(a1), "r"(a2), "r"(a3), "r"(b0), "r"(b1));
}

// ---------------- prep: quantize + pack the large weights ----------------
__global__ void prep_kernel(const float* __restrict__ dw2,
                            const float* __restrict__ pw2, const float* __restrict__ dw3,
                            const float* __restrict__ pw3, const float* __restrict__ wc1,
                            const float* __restrict__ wc2)
{
    int t = blockIdx.x * blockDim.x + threadIdx.x;
    int NT = gridDim.x * blockDim.x;
    for (int i = t; i < 512; i += NT) {
        int oc = i >> 3, g = i & 7; const float* p = pw2 + oc*32 + g*4;
        gPW2[i] = pack4(qw4c(p[0]), qw4c(p[1]), qw4c(p[2]), qw4c(p[3]));
    }
    for (int i = t; i < 2048; i += NT) {
        int oc = i >> 4, g = i & 15; const float* p = pw3 + oc*64 + g*4;
        gPW3[i] = pack4(qw4c(p[0]), qw4c(p[1]), qw4c(p[2]), qw4c(p[3]));
    }
    for (int i = t; i < 8192; i += NT) {
        int g = i >> 8, oc = i & 255; const float* p = wc1 + oc*128 + g*4;
        gFC1[i] = pack4(qw4c(p[0]), qw4c(p[1]), qw4c(p[2]), qw4c(p[3]));
    }
    for (int i = t; i < 640; i += NT) {
        int oc = i / 64, g = i & 63; const float* p = wc2 + oc*256 + g*4;
        gFC2[i] = pack4(qw4c(p[0]), qw4c(p[1]), qw4c(p[2]), qw4c(p[3]));
    }
    for (int i = t; i < 96; i += NT) {
        int c = i / 3, ky = i % 3; const float* p = dw2 + c*9 + ky*3;
        gDW2r[i] = pack4(qw4c(p[0]), qw4c(p[1]), qw4c(p[2]), 0);
    }
    for (int i = t; i < 192; i += NT) {
        int c = i / 3, ky = i % 3; const float* p = dw3 + c*9 + ky*3;
        gDW3r[i] = pack4(qw4c(p[0]), qw4c(p[1]), qw4c(p[2]), 0);
    }
    cudaTriggerProgrammaticLaunchCompletion();
}

// ---------------- main fused kernel ----------------
// SMEM (27968 B): R0 [0,8192) / R1 [8192,16384) alternate stage buffers.
//  PW2w [16384,18432) PW3w [18432,26624) PW1w [26624,26752)
//  DW1r [26752,26792) DW2r [26792,27176) DW3r [27176,27944) W0w [27944,27960)
#define SM_BYTES 27968

__global__ __launch_bounds__(QT, 7)
void qnet_kernel(const float* __restrict__ x, float* __restrict__ out,
                 const float* __restrict__ w0f, const float* __restrict__ dw1f,
                 const float* __restrict__ pw1f)
{
    extern __shared__ unsigned char sm[];
    const int tid = threadIdx.x;
    const int b   = blockIdx.x;

    signed char*   B    = (signed char*)(sm);           // conv0 out [c][1024], x-packed
    uint32_t*      P1   = (uint32_t*)(sm + 8192);       // dw1 out, rotated rows
    signed char*   D    = (signed char*)(sm);           // pw1 out [oc][256], bit-flip swz
    uint32_t*      P2   = (uint32_t*)(sm + 8192);       // dw2 out [g][qidx'] row-XOR swz
    signed char*   D3   = (signed char*)(sm);           // pw2 out [oc][64], chan-XOR swz
    uint32_t*      P3   = (uint32_t*)(sm + 8192);       // dw3 out [g][px^sw] 4ch words
    unsigned char* Vb   = (unsigned char*)(sm);         // 128 (R0; D3 dead by then)
    unsigned char* V2b  = (unsigned char*)(sm + 256);   // 256
    uint32_t*      PW2w = (uint32_t*)(sm + 16384);
    uint32_t*      PW3w = (uint32_t*)(sm + 18432);
    uint32_t*      PW1w = (uint32_t*)(sm + 26624);
    uint32_t*      DW1r = (uint32_t*)(sm + 26752);
    uint32_t*      DW2r = (uint32_t*)(sm + 26792);
    uint32_t*      DW3r = (uint32_t*)(sm + 27176);
    uint32_t*      W0w  = (uint32_t*)(sm + 27944);

    // ---- input loads + quant/pack AND per-CTA small-weight quantization ----
    // (independent of prep_kernel's output; runs under PDL overlap)
    const float4* xv = (const float4*)(x + (size_t)b * 3072);
    int aA[4], aB[4];
    {
        float4 v0 = xv[tid], v1 = xv[256 + tid], v2 = xv[512 + tid];
        aA[0] = (int)pack4(qa8c(v0.x), qa8c(v1.x), qa8c(v2.x), 0);
        aA[1] = (int)pack4(qa8c(v0.y), qa8c(v1.y), qa8c(v2.y), 0);
        aA[2] = (int)pack4(qa8c(v0.z), qa8c(v1.z), qa8c(v2.z), 0);
        aA[3] = (int)pack4(qa8c(v0.w), qa8c(v1.w), qa8c(v2.w), 0);
    }
    if (tid < 64) {
        int q = tid + 192;
        float4 v0 = xv[q], v1 = xv[256 + q], v2 = xv[512 + q];
        aB[0] = (int)pack4(qa8c(v0.x), qa8c(v1.x), qa8c(v2.x), 0);
        aB[1] = (int)pack4(qa8c(v0.y), qa8c(v1.y), qa8c(v2.y), 0);
        aB[2] = (int)pack4(qa8c(v0.z), qa8c(v1.z), qa8c(v2.z), 0);
        aB[3] = (int)pack4(qa8c(v0.w), qa8c(v1.w), qa8c(v2.w), 0);
    }
    if (tid < 3) {
        const float* p = w0f + tid * 3;
        W0w[tid] = pack4(qw8c(p[0]), qw8c(p[1]), qw8c(p[2]), 0);
    } else if (tid >= 4 && tid < 13) {
        int i = tid - 4;                   // dw1 row-packed [c*3+ky]
        const float* p = dw1f + i * 3;
        DW1r[i] = pack4(qw4c(p[0]), qw4c(p[1]), qw4c(p[2]), 0);
    } else if (tid >= 64 && tid < 96) {
        int oc = tid - 64;
        const float* p = pw1f + oc * 3;
        PW1w[oc] = pack4(qw4c(p[0]), qw4c(p[1]), qw4c(p[2]), 0);
    }
    __syncthreads();

    // ---- conv0 (1x1, 3->3) + act4 requant ----
    {
        int w0c = (int)W0w[0], w1c = (int)W0w[1], w2c = (int)W0w[2];
        {
            int c00 = clampi(rq5(__dp4a(aA[0], w0c, 0)), -8, 7);
            int c01 = clampi(rq5(__dp4a(aA[1], w0c, 0)), -8, 7);
            int c02 = clampi(rq5(__dp4a(aA[2], w0c, 0)), -8, 7);
            int c03 = clampi(rq5(__dp4a(aA[3], w0c, 0)), -8, 7);
            ((uint32_t*)B)[tid] = pack4(c00, c01, c02, c03);
            c00 = clampi(rq5(__dp4a(aA[0], w1c, 0)), -8, 7);
            c01 = clampi(rq5(__dp4a(aA[1], w1c, 0)), -8, 7);
            c02 = clampi(rq5(__dp4a(aA[2], w1c, 0)), -8, 7);
            c03 = clampi(rq5(__dp4a(aA[3], w1c, 0)), -8, 7);
            ((uint32_t*)B)[256 + tid] = pack4(c00, c01, c02, c03);
            c00 = clampi(rq5(__dp4a(aA[0], w2c, 0)), -8, 7);
            c01 = clampi(rq5(__dp4a(aA[1], w2c, 0)), -8, 7);
            c02 = clampi(rq5(__dp4a(aA[2], w2c, 0)), -8, 7);
            c03 = clampi(rq5(__dp4a(aA[3], w2c, 0)), -8, 7);
            ((uint32_t*)B)[512 + tid] = pack4(c00, c01, c02, c03);
        }
        if (tid < 64) {
            int q = tid + 192;
            int c00 = clampi(rq5(__dp4a(aB[0], w0c, 0)), -8, 7);
            int c01 = clampi(rq5(__dp4a(aB[1], w0c, 0)), -8, 7);
            int c02 = clampi(rq5(__dp4a(aB[2], w0c, 0)), -8, 7);
            int c03 = clampi(rq5(__dp4a(aB[3], w0c, 0)), -8, 7);
            ((uint32_t*)B)[q] = pack4(c00, c01, c02, c03);
            c00 = clampi(rq5(__dp4a(aB[0], w1c, 0)), -8, 7);
            c01 = clampi(rq5(__dp4a(aB[1], w1c, 0)), -8, 7);
            c02 = clampi(rq5(__dp4a(aB[2], w1c, 0)), -8, 7);
            c03 = clampi(rq5(__dp4a(aB[3], w1c, 0)), -8, 7);
            ((uint32_t*)B)[256 + q] = pack4(c00, c01, c02, c03);
            c00 = clampi(rq5(__dp4a(aB[0], w2c, 0)), -8, 7);
            c01 = clampi(rq5(__dp4a(aB[1], w2c, 0)), -8, 7);
            c02 = clampi(rq5(__dp4a(aB[2], w2c, 0)), -8, 7);
            c03 = clampi(rq5(__dp4a(aB[3], w2c, 0)), -8, 7);
            ((uint32_t*)B)[512 + q] = pack4(c00, c01, c02, c03);
        }
    }
    __syncthreads();

    // ---- dw1: depthwise 3x3, 3ch @32x32. Item = 1 word (4 px), all 3 ch.
    //      P1 rows rotated by 4*((y>>1)&1) words. 256 items over 192 threads. ----
    for (int it = tid; it < 256; it += QT) {
        int y = it >> 3, wx = it & 7;
        int res[3][4];
        #pragma unroll
        for (int c = 0; c < 3; c++) {
            int s0 = 0, s1 = 0, s2 = 0, s3 = 0;
            #pragma unroll
            for (int ky = 0; ky < 3; ky++) {
                int yy = y + ky - 1;
                if ((unsigned)yy <= 31u) {
                    const uint32_t* rp = (const uint32_t*)(B + c * 1024 + yy * 32);
                    uint32_t cur  = rp[wx];
                    uint32_t prev = wx ? rp[wx - 1] : 0u;
                    uint32_t nxt  = (wx < 7) ? rp[wx + 1] : 0u;
                    int wv = (int)DW1r[c * 3 + ky];
                    s0 = __dp4a((int)__byte_perm(cur, prev, 0x0107), wv, s0);
                    s1 = __dp4a((int)cur,                            wv, s1);
                    s2 = __dp4a((int)(cur >> 8),                     wv, s2);
                    s3 = __dp4a((int)__byte_perm(cur, nxt, 0x0432),  wv, s3);
                }
            }
            res[c][0] = clampi(rq2(s0), -8, 7);
            res[c][1] = clampi(rq2(s1), -8, 7);
            res[c][2] = clampi(rq2(s2), -8, 7);
            res[c][3] = clampi(rq2(s3), -8, 7);
        }
        uint4 o;
        o.x = pack4(res[0][0], res[1][0], res[2][0], 0);
        o.y = pack4(res[0][1], res[1][1], res[2][1], 0);
        o.z = pack4(res[0][2], res[1][2], res[2][2], 0);
        o.w = pack4(res[0][3], res[1][3], res[2][3], 0);
        int off = (wx * 4 + ((y >> 1) & 1) * 4) & 31;   // row rotation
        *(uint4*)(P1 + y * 32 + off) = o;
    }
    __syncthreads();

    // ---- pw1 (3->32) + relu + maxpool2 + act4 requant ----
    // Item = (8 oc) x (4 pooled px). 256 items over 192 threads.
    // D stored with bit-flip swizzle: word q -> q ^ ((q>>5&1)<<2).
    for (int it = tid; it < 256; it += QT) {
        int q   = it & 63;
        int ocg = it >> 6;
        int Y   = q >> 2;
        int X   = q & 3;
        int o0 = (8 * X + 4 * (Y & 1)) & 31;
        int o1 = (o0 + 4) & 31;
        const uint32_t* row0 = P1 + 64 * Y;
        const uint32_t* row1 = row0 + 32;
        uint4 A0 = *(const uint4*)(row0 + o0);
        uint4 A1 = *(const uint4*)(row0 + o1);
        uint4 B0 = *(const uint4*)(row1 + o0);
        uint4 B1 = *(const uint4*)(row1 + o1);
        int ta[8] = {(int)A0.x,(int)A0.y,(int)A0.z,(int)A0.w,
                     (int)A1.x,(int)A1.y,(int)A1.z,(int)A1.w};
        int tb[8] = {(int)B0.x,(int)B0.y,(int)B0.z,(int)B0.w,
                     (int)B1.x,(int)B1.y,(int)B1.z,(int)B1.w};
        uint32_t* Dw = (uint32_t*)D;
        int qs = q ^ (((q >> 5) & 1) << 2);   // bit-flip swizzle
        #pragma unroll
        for (int oo = 0; oo < 8; oo++) {
            int oc = ocg * 8 + oo;
            int wv = (int)PW1w[oc];
            int m[4];
            #pragma unroll
            for (int j = 0; j < 4; j++) {
                int s0 = __dp4a(ta[2*j],     wv, 0);
                int s1 = __dp4a(ta[2*j + 1], wv, 0);
                int s2 = __dp4a(tb[2*j],     wv, 0);
                int s3 = __dp4a(tb[2*j + 1], wv, 0);
                m[j] = max(max(max(s0, s1), max(s2, s3)), 0);
            }
            Dw[oc * 64 + qs] = fq4x4(pack4(m[0], m[1], m[2], m[3]));
        }
    }

    // ---- wait for prep kernel (PDL): first use of the large packed weights ----
    cudaGridDependencySynchronize();

    // ---- stage large packed weights (L2-hot), vectorized ----
    if (tid < 128) ((uint4*)PW2w)[tid] = ((const uint4*)gPW2)[tid];
    for (int i = tid; i < 512; i += QT)
        ((uint4*)PW3w)[i] = ((const uint4*)gPW3)[i];
    if (tid < 96)  DW2r[tid] = gDW2r[tid];
    DW3r[tid] = gDW3r[tid];   // exactly 192
    __syncthreads();

    // ---- dw2: depthwise 3x3, 32ch @16x16. Item = 8-px half-row of 1 ch.
    //      D loads use bit-flip swizzle; P2 stores use row-XOR swizzle. ----
    for (int item = tid; item < 1024; item += QT) {
        int c = item >> 5;
        int r = item & 31;
        int y = r >> 1, h = r & 1;
        const uint32_t* chb = (const uint32_t*)(D + c * 256);
        int acc[8] = {};
        #pragma unroll
        for (int ky = 0; ky < 3; ky++) {
            int yy = y + ky - 1;
            if ((unsigned)yy <= 15u) {
                int base = yy * 4;
                int xw = (yy & 8) >> 1;    // bit-flip swizzle
                uint32_t c0 = chb[(base + 2 * h) ^ xw];
                uint32_t c1 = chb[(base + 2 * h + 1) ^ xw];
                uint32_t lf = h ? chb[(base + 1) ^ xw] : 0u;
                uint32_t rt = h ? 0u : chb[(base + 2) ^ xw];
                int wv = (int)DW2r[c * 3 + ky];
                acc[0] = __dp4a((int)__byte_perm(c0, lf, 0x0107), wv, acc[0]);
                acc[1] = __dp4a((int)c0,                          wv, acc[1]);
                acc[2] = __dp4a((int)(c0 >> 8),                   wv, acc[2]);
                acc[3] = __dp4a((int)__byte_perm(c0, c1, 0x0432), wv, acc[3]);
                acc[4] = __dp4a((int)__byte_perm(c1, c0, 0x0107), wv, acc[4]);
                acc[5] = __dp4a((int)c1,                          wv, acc[5]);
                acc[6] = __dp4a((int)(c1 >> 8),                   wv, acc[6]);
                acc[7] = __dp4a((int)__byte_perm(c1, rt, 0x0432), wv, acc[7]);
            }
        }
        int g = c >> 2, ln = c & 3;
        int xmask = (((y >> 1) & 7) << 2) ^ ((g & 3) * 8);  // row-XOR + kgroup swizzle
        #pragma unroll
        for (int j = 0; j < 8; j++) {
            int xpix = h * 8 + j;
            int qidx = ((y >> 1) * 8 + (xpix >> 1)) * 4 + (y & 1) * 2 + (xpix & 1);
            ((signed char*)P2)[(g * 256 + (qidx ^ xmask)) * 4 + ln] =
                (signed char)clampi(rq2(acc[j]), -8, 7);
        }
    }
    __syncthreads();

    // ---- pw2 (32->64) via IMMA + relu + maxpool2 + requant ----
    // 8 warp-jobs over 6 warps. P2 read row-XOR swizzle; D3 store chan-XOR swizzle.
    {
        int warp = tid >> 5, lane = tid & 31;
        int li4 = lane >> 2, lm4 = lane & 3;
        int sw = lm4 * 8;
        for (int w = warp; w < 8; w += 6) {
            int m0 = (w & 3) * 16;
            int nh = w >> 2;
            int a0w = (int)PW2w[(m0 + li4) * 8 + lm4];
            int a1w = (int)PW2w[(m0 + li4 + 8) * 8 + lm4];
            int a2w = (int)PW2w[(m0 + li4) * 8 + 4 + lm4];
            int a3w = (int)PW2w[(m0 + li4 + 8) * 8 + 4 + lm4];
            #pragma unroll
            for (int t = 0; t < 16; t++) {
                int n0 = (nh * 16 + t) * 8;
                int nn = n0 + li4;
                int pxs = nn ^ (((nn >> 5) & 7) << 2) ^ sw;   // row-XOR swizzle
                int b0 = (int)P2[lm4 * 256 + pxs];
                int b1 = (int)P2[(4 + lm4) * 256 + pxs];
                int d0 = 0, d1 = 0, d2 = 0, d3 = 0;
                mma_s8(d0, d1, d2, d3, a0w, a1w, a2w, a3w, b0, b1);
                int mA = max(d0, d1);
                int mB = max(d2, d3);
                mA = max(mA, __shfl_xor_sync(0xffffffffu, mA, 1));
                mB = max(mB, __shfl_xor_sync(0xffffffffu, mB, 1));
                if (!(lane & 1)) {
                    int q = n0 / 4 + (lm4 >> 1);
                    int qs = ((((q >> 2) ^ li4) & 15) << 2) | (q & 3);  // chan-XOR swz
                    D3[(m0 + li4) * 64 + qs]     = (signed char)fq4(mA);
                    D3[(m0 + li4 + 8) * 64 + qs] = (signed char)fq4(mB);
                }
            }
        }
    }
    __syncthreads();

    // ---- dw3: depthwise 3x3, 64ch @8x8. Item = full 8-px row of 1 ch.
    //      D3 loads apply channel-XOR swizzle. ----
    for (int item = tid; item < 512; item += QT) {
        int c = item >> 3;
        int y = item & 7;
        const uint32_t* chb = (const uint32_t*)D3 + c * 16;
        int xc = c & 7;                    // channel-XOR swizzle
        int acc[8] = {};
        #pragma unroll
        for (int ky = 0; ky < 3; ky++) {
            int yy = y + ky - 1;
            if ((unsigned)yy <= 7u) {
                uint32_t c0 = chb[(yy * 2) ^ xc];
                uint32_t c1 = chb[(yy * 2 + 1) ^ xc];
                int wv = (int)DW3r[c * 3 + ky];
                acc[0] = __dp4a((int)__byte_perm(c0, 0u, 0x0107), wv, acc[0]);
                acc[1] = __dp4a((int)c0,                          wv, acc[1]);
                acc[2] = __dp4a((int)(c0 >> 8),                   wv, acc[2]);
                acc[3] = __dp4a((int)__byte_perm(c0, c1, 0x0432), wv, acc[3]);
                acc[4] = __dp4a((int)__byte_perm(c1, c0, 0x0107), wv, acc[4]);
                acc[5] = __dp4a((int)c1,                          wv, acc[5]);
                acc[6] = __dp4a((int)(c1 >> 8),                   wv, acc[6]);
                acc[7] = __dp4a((int)__byte_perm(c1, 0u, 0x0432), wv, acc[7]);
            }
        }
        int g = c >> 2, ln = c & 3;
        int sw = (g & 3) * 8;
        #pragma unroll
        for (int j = 0; j < 8; j++) {
            int px = y * 8 + j;
            ((signed char*)P3)[(g * 64 + (px ^ sw)) * 4 + ln] =
                (signed char)clampi(rq2(acc[j]), -8, 7);
        }
    }
    __syncthreads();

    // ---- pw3 (64->128) via IMMA + global maxpool in registers -> Vb ----
    // 8 oc-tile jobs over 6 warps.
    {
        int warp = tid >> 5, lane = tid & 31;
        int li4 = lane >> 2, lm4 = lane & 3;
        int sw = lm4 * 8;
        for (int w = warp; w < 8; w += 6) {
            int m0 = w * 16;
            int A[2][4];
            #pragma unroll
            for (int kt = 0; kt < 2; kt++) {
                A[kt][0] = (int)PW3w[(m0 + li4) * 16 + kt * 8 + lm4];
                A[kt][1] = (int)PW3w[(m0 + li4 + 8) * 16 + kt * 8 + lm4];
                A[kt][2] = (int)PW3w[(m0 + li4) * 16 + kt * 8 + 4 + lm4];
                A[kt][3] = (int)PW3w[(m0 + li4 + 8) * 16 + kt * 8 + 4 + lm4];
            }
            int mA = INT_MIN, mB = INT_MIN;
            #pragma unroll
            for (int t = 0; t < 8; t++) {
                int pxs = (t * 8 + li4) ^ sw;
                int d0 = 0, d1 = 0, d2 = 0, d3 = 0;
                #pragma unroll
                for (int kt = 0; kt < 2; kt++) {
                    int b0 = (int)P3[(kt * 8 + lm4) * 64 + pxs];
                    int b1 = (int)P3[(kt * 8 + 4 + lm4) * 64 + pxs];
                    mma_s8(d0, d1, d2, d3, A[kt][0], A[kt][1], A[kt][2], A[kt][3], b0, b1);
                }
                mA = max(mA, max(d0, d1));
                mB = max(mB, max(d2, d3));
            }
            mA = max(mA, __shfl_xor_sync(0xffffffffu, mA, 1));
            mA = max(mA, __shfl_xor_sync(0xffffffffu, mA, 2));
            mB = max(mB, __shfl_xor_sync(0xffffffffu, mB, 1));
            mB = max(mB, __shfl_xor_sync(0xffffffffu, mB, 2));
            if (lm4 == 0) {
                Vb[m0 + li4]     = (unsigned char)fq4(mA);
                Vb[m0 + li4 + 8] = (unsigned char)fq4(mB);
            }
        }
    }
    __syncthreads();

    // ---- fc1: 128->256 (weights streamed from global, coalesced, L2-hot) ----
    for (int o = tid; o < 256; o += QT) {
        const uint32_t* Vw = (const uint32_t*)Vb;
        int S = 0;
        #pragma unroll 8
        for (int g = 0; g < 32; g++)
            S = __dp4a((int)Vw[g], (int)gFC1[g * 256 + o], S);
        V2b[o] = (unsigned char)fq4(S);
    }
    __syncthreads();

    // ---- fc2: 256->10, output int8 quant (o = S*0.125 -> round(o*16) = 2S) ----
    if (tid < 160) {
        int oc = tid >> 4, l = tid & 15;
        const uint32_t* Vw = (const uint32_t*)V2b;
        int S = 0;
        #pragma unroll
        for (int k = 0; k < 4; k++) {
            int g = l + k * 16;
            S = __dp4a((int)Vw[g], (int)gFC2[oc * 64 + g], S);
        }
        #pragma unroll
        for (int off = 8; off; off >>= 1) S += __shfl_down_sync(0xffffffffu, S, off, 16);
        if (l == 0) {
            int o = clampi(2 * S, -128, 127);
            out[(size_t)b * 10 + oc] = (float)o * 0.0625f;
        }
    }
}

extern "C" void kernel_launch(void* const* d_in, const int* in_sizes, int n_in,
                              void* d_out, int out_size)
{
    (void)in_sizes; (void)n_in; (void)out_size;
    const float* x   = (const float*)d_in[0];
    const float* w0  = (const float*)d_in[1];
    const float* dw1 = (const float*)d_in[2];
    const float* pw1 = (const float*)d_in[3];
    const float* dw2 = (const float*)d_in[4];
    const float* pw2 = (const float*)d_in[5];
    const float* dw3 = (const float*)d_in[6];
    const float* pw3 = (const float*)d_in[7];
    const float* wc1 = (const float*)d_in[8];
    const float* wc2 = (const float*)d_in[9];
    float* out = (float*)d_out;

    prep_kernel<<<48, PTHREADS>>>(dw2, pw2, dw3, pw3, wc1, wc2);

    // qnet launched with Programmatic Stream Serialization: its CTAs begin
    // executing conv0/dw1/pw1 (per-CTA-quantized small weights) while prep
    // finishes; cudaGridDependencySynchronize() before dw2 orders the large
    // weight reads after prep's trigger.
    cudaLaunchConfig_t cfg = {};
    cfg.gridDim = dim3(1024, 1, 1);
    cfg.blockDim = dim3(QT, 1, 1);
    cfg.dynamicSmemBytes = SM_BYTES;
    cfg.stream = 0;
    cudaLaunchAttribute attrs[1];
    attrs[0].id = cudaLaunchAttributeProgrammaticStreamSerialization;
    attrs[0].val.programmaticStreamSerializationAllowed = 1;
    cfg.attrs = attrs;
    cfg.numAttrs = 1;
    cudaLaunchKernelEx(&cfg, qnet_kernel, x, out, w0, dw1, pw1);
}

// round 14
// speedup vs baseline: 1.0609x; 1.0609x over previous
#include <cuda_runtime.h>
#include <cstdint>

// Fully fused quantized CIFAR-10 net. Depthwise via dp4a, pw2/pw3 via IMMA
// mma.m16n8k32.s8 with register-resident pooling; bank-conflict-free swizzles.
// 128 threads x 8 CTAs/SM: whole 1024-CTA grid resident in ONE wave (148*8=1184),
// with every stage an exact multiple of the CTA (no bound checks, no warp
// imbalance). PDL overlaps prep with conv0..pw1. Round-half-even ==> bit-exact.

#define PTHREADS 256   // prep kernel
#define QT 128         // qnet threads per CTA

// ---------------- packed weight globals (written by prep_kernel) ----------------
__device__ __align__(16) uint32_t gPW2[512];   // pw2 [oc*8+g]: 4 ic codes
__device__ __align__(16) uint32_t gPW3[2048];  // pw3 [oc*16+g]: 4 ic codes
__device__ uint32_t gFC1[8192];  // fc1 [g*256+oc]: 4 ic codes (coalesced by oc)
__device__ uint32_t gFC2[640];   // fc2 [oc*64+g]: 4 ic codes
__device__ uint32_t gDW2r[96];   // dw2 row-packed [c*3+ky]
__device__ uint32_t gDW3r[192];  // dw3 row-packed [c*3+ky]

// ---------------- helpers ----------------
__device__ __forceinline__ int clampi(int v, int lo, int hi) { return min(max(v, lo), hi); }
__device__ __forceinline__ uint32_t pack4(int a, int b, int c, int d) {
    return (uint32_t)(a & 0xFF) | ((uint32_t)(b & 0xFF) << 8) |
           ((uint32_t)(c & 0xFF) << 16) | ((uint32_t)(d & 0xFF) << 24);
}
__device__ __forceinline__ int qw4c(float w) {
    float q = rintf(w * 4.f); return (int)fmaxf(-8.f, fminf(7.f, q));
}
__device__ __forceinline__ int qw8c(float w) {
    float q = rintf(w * 4.f); return (int)fmaxf(-128.f, fminf(127.f, q));
}
__device__ __forceinline__ int qa8c(float v) {
    return clampi(__float2int_rn(v * 16.f), -128, 127);
}
// branch-free round-half-even of S/4
__device__ __forceinline__ int rq2(int S) {
    return (S + 1 + ((S >> 2) & 1)) >> 2;
}
// branch-free round-half-even of S/32
__device__ __forceinline__ int rq5(int S) {
    return (S + 15 + ((S >> 5) & 1)) >> 5;
}
// fused QuantReLU4 + S_ACT4 requant
__device__ __forceinline__ int fq4(int S) {
    int m = max(S, 0);
    return min((m + 1 + ((m >> 2) & 1)) >> 2, 7);
}
// packed fq4 on 4 unsigned bytes (values in [0,252])
__device__ __forceinline__ uint32_t fq4x4(uint32_t p) {
    uint32_t inc = ((p >> 2) & 0x01010101u) + 0x01010101u;
    uint32_t t = __vadd4(p, inc);
    return __vminu4((t >> 2) & 0x3F3F3F3Fu, 0x07070707u);
}
// s8 tensor-core mma, D += A*B (s32 accumulate)
__device__ __forceinline__ void mma_s8(int& d0, int& d1, int& d2, int& d3,
                                       int a0, int a1, int a2, int a3,
                                       int b0, int b1) {
    asm volatile("mma.sync.aligned.m16n8k32.row.col.s32.s8.s8.s32 "
                 "{%0,%1,%2,%3}, {%4,%5,%6,%7}, {%8,%9}, {%0,%1,%2,%3};"
                 : "+r"(d0), "+r"(d1), "+r"(d2), "+r"(d3)
                 : "r"(a0), "r"(a1), "r"(a2), "r"(a3), "r"(b0), "r"(b1));
}

// ---------------- prep: quantize + pack the large weights ----------------
__global__ void prep_kernel(const float* __restrict__ dw2,
                            const float* __restrict__ pw2, const float* __restrict__ dw3,
                            const float* __restrict__ pw3, const float* __restrict__ wc1,
                            const float* __restrict__ wc2)
{
    int t = blockIdx.x * blockDim.x + threadIdx.x;
    int NT = gridDim.x * blockDim.x;
    for (int i = t; i < 512; i += NT) {
        int oc = i >> 3, g = i & 7; const float* p = pw2 + oc*32 + g*4;
        gPW2[i] = pack4(qw4c(p[0]), qw4c(p[1]), qw4c(p[2]), qw4c(p[3]));
    }
    for (int i = t; i < 2048; i += NT) {
        int oc = i >> 4, g = i & 15; const float* p = pw3 + oc*64 + g*4;
        gPW3[i] = pack4(qw4c(p[0]), qw4c(p[1]), qw4c(p[2]), qw4c(p[3]));
    }
    for (int i = t; i < 8192; i += NT) {
        int g = i >> 8, oc = i & 255; const float* p = wc1 + oc*128 + g*4;
        gFC1[i] = pack4(qw4c(p[0]), qw4c(p[1]), qw4c(p[2]), qw4c(p[3]));
    }
    for (int i = t; i < 640; i += NT) {
        int oc = i / 64, g = i & 63; const float* p = wc2 + oc*256 + g*4;
        gFC2[i] = pack4(qw4c(p[0]), qw4c(p[1]), qw4c(p[2]), qw4c(p[3]));
    }
    for (int i = t; i < 96; i += NT) {
        int c = i / 3, ky = i % 3; const float* p = dw2 + c*9 + ky*3;
        gDW2r[i] = pack4(qw4c(p[0]), qw4c(p[1]), qw4c(p[2]), 0);
    }
    for (int i = t; i < 192; i += NT) {
        int c = i / 3, ky = i % 3; const float* p = dw3 + c*9 + ky*3;
        gDW3r[i] = pack4(qw4c(p[0]), qw4c(p[1]), qw4c(p[2]), 0);
    }
    cudaTriggerProgrammaticLaunchCompletion();
}

// ---------------- main fused kernel ----------------
// SMEM (27968 B): R0 [0,8192) / R1 [8192,16384) alternate stage buffers.
//  PW2w [16384,18432) PW3w [18432,26624) PW1w [26624,26752)
//  DW1r [26752,26792) DW2r [26792,27176) DW3r [27176,27944) W0w [27944,27960)
#define SM_BYTES 27968

__global__ __launch_bounds__(QT, 8)
void qnet_kernel(const float* __restrict__ x, float* __restrict__ out,
                 const float* __restrict__ w0f, const float* __restrict__ dw1f,
                 const float* __restrict__ pw1f)
{
    extern __shared__ unsigned char sm[];
    const int tid = threadIdx.x;
    const int b   = blockIdx.x;

    signed char*   B    = (signed char*)(sm);           // conv0 out [c][1024], x-packed
    uint32_t*      P1   = (uint32_t*)(sm + 8192);       // dw1 out, rotated rows
    signed char*   D    = (signed char*)(sm);           // pw1 out [oc][256], bit-flip swz
    uint32_t*      P2   = (uint32_t*)(sm + 8192);       // dw2 out [g][qidx'] row-XOR swz
    signed char*   D3   = (signed char*)(sm);           // pw2 out [oc][64], chan-XOR swz
    uint32_t*      P3   = (uint32_t*)(sm + 8192);       // dw3 out [g][px^sw] 4ch words
    unsigned char* Vb   = (unsigned char*)(sm);         // 128 (R0; D3 dead by then)
    unsigned char* V2b  = (unsigned char*)(sm + 256);   // 256
    uint32_t*      PW2w = (uint32_t*)(sm + 16384);
    uint32_t*      PW3w = (uint32_t*)(sm + 18432);
    uint32_t*      PW1w = (uint32_t*)(sm + 26624);
    uint32_t*      DW1r = (uint32_t*)(sm + 26752);
    uint32_t*      DW2r = (uint32_t*)(sm + 26792);
    uint32_t*      DW3r = (uint32_t*)(sm + 27176);
    uint32_t*      W0w  = (uint32_t*)(sm + 27944);

    // ---- input loads + quant/pack AND per-CTA small-weight quantization ----
    // (independent of prep_kernel's output; runs under PDL overlap)
    const float4* xv = (const float4*)(x + (size_t)b * 3072);
    int aP[2][4];
    #pragma unroll
    for (int k = 0; k < 2; k++) {
        int p = tid + k * 128;
        float4 v0 = xv[p], v1 = xv[256 + p], v2 = xv[512 + p];
        aP[k][0] = (int)pack4(qa8c(v0.x), qa8c(v1.x), qa8c(v2.x), 0);
        aP[k][1] = (int)pack4(qa8c(v0.y), qa8c(v1.y), qa8c(v2.y), 0);
        aP[k][2] = (int)pack4(qa8c(v0.z), qa8c(v1.z), qa8c(v2.z), 0);
        aP[k][3] = (int)pack4(qa8c(v0.w), qa8c(v1.w), qa8c(v2.w), 0);
    }
    if (tid < 3) {
        const float* p = w0f + tid * 3;
        W0w[tid] = pack4(qw8c(p[0]), qw8c(p[1]), qw8c(p[2]), 0);
    } else if (tid >= 4 && tid < 13) {
        int i = tid - 4;                   // dw1 row-packed [c*3+ky]
        const float* p = dw1f + i * 3;
        DW1r[i] = pack4(qw4c(p[0]), qw4c(p[1]), qw4c(p[2]), 0);
    } else if (tid >= 64 && tid < 96) {
        int oc = tid - 64;
        const float* p = pw1f + oc * 3;
        PW1w[oc] = pack4(qw4c(p[0]), qw4c(p[1]), qw4c(p[2]), 0);
    }
    __syncthreads();

    // ---- conv0 (1x1, 3->3) + act4 requant. 2 exact items/thread ----
    {
        int w0c = (int)W0w[0], w1c = (int)W0w[1], w2c = (int)W0w[2];
        #pragma unroll
        for (int k = 0; k < 2; k++) {
            int p = tid + k * 128;
            int c0 = clampi(rq5(__dp4a(aP[k][0], w0c, 0)), -8, 7);
            int c1 = clampi(rq5(__dp4a(aP[k][1], w0c, 0)), -8, 7);
            int c2 = clampi(rq5(__dp4a(aP[k][2], w0c, 0)), -8, 7);
            int c3 = clampi(rq5(__dp4a(aP[k][3], w0c, 0)), -8, 7);
            ((uint32_t*)B)[p] = pack4(c0, c1, c2, c3);
            c0 = clampi(rq5(__dp4a(aP[k][0], w1c, 0)), -8, 7);
            c1 = clampi(rq5(__dp4a(aP[k][1], w1c, 0)), -8, 7);
            c2 = clampi(rq5(__dp4a(aP[k][2], w1c, 0)), -8, 7);
            c3 = clampi(rq5(__dp4a(aP[k][3], w1c, 0)), -8, 7);
            ((uint32_t*)B)[256 + p] = pack4(c0, c1, c2, c3);
            c0 = clampi(rq5(__dp4a(aP[k][0], w2c, 0)), -8, 7);
            c1 = clampi(rq5(__dp4a(aP[k][1], w2c, 0)), -8, 7);
            c2 = clampi(rq5(__dp4a(aP[k][2], w2c, 0)), -8, 7);
            c3 = clampi(rq5(__dp4a(aP[k][3], w2c, 0)), -8, 7);
            ((uint32_t*)B)[512 + p] = pack4(c0, c1, c2, c3);
        }
    }
    __syncthreads();

    // ---- dw1: depthwise 3x3, 3ch @32x32. Item = 1 word (4 px), all 3 ch.
    //      256 items = 2 exact/thread. P1 rows rotated by 4*((y>>1)&1) words. ----
    #pragma unroll
    for (int k = 0; k < 2; k++) {
        int it = tid + k * 128;
        int y = it >> 3, wx = it & 7;
        int res[3][4];
        #pragma unroll
        for (int c = 0; c < 3; c++) {
            int s0 = 0, s1 = 0, s2 = 0, s3 = 0;
            #pragma unroll
            for (int ky = 0; ky < 3; ky++) {
                int yy = y + ky - 1;
                if ((unsigned)yy <= 31u) {
                    const uint32_t* rp = (const uint32_t*)(B + c * 1024 + yy * 32);
                    uint32_t cur  = rp[wx];
                    uint32_t prev = wx ? rp[wx - 1] : 0u;
                    uint32_t nxt  = (wx < 7) ? rp[wx + 1] : 0u;
                    int wv = (int)DW1r[c * 3 + ky];
                    s0 = __dp4a((int)__byte_perm(cur, prev, 0x0107), wv, s0);
                    s1 = __dp4a((int)cur,                            wv, s1);
                    s2 = __dp4a((int)(cur >> 8),                     wv, s2);
                    s3 = __dp4a((int)__byte_perm(cur, nxt, 0x0432),  wv, s3);
                }
            }
            res[c][0] = clampi(rq2(s0), -8, 7);
            res[c][1] = clampi(rq2(s1), -8, 7);
            res[c][2] = clampi(rq2(s2), -8, 7);
            res[c][3] = clampi(rq2(s3), -8, 7);
        }
        uint4 o;
        o.x = pack4(res[0][0], res[1][0], res[2][0], 0);
        o.y = pack4(res[0][1], res[1][1], res[2][1], 0);
        o.z = pack4(res[0][2], res[1][2], res[2][2], 0);
        o.w = pack4(res[0][3], res[1][3], res[2][3], 0);
        int off = (wx * 4 + ((y >> 1) & 1) * 4) & 31;   // row rotation
        *(uint4*)(P1 + y * 32 + off) = o;
    }
    __syncthreads();

    // ---- pw1 (3->32) + relu + maxpool2 + act4 requant ----
    // Item = (8 oc) x (4 pooled px). 256 items = 2 exact/thread.
    // D stored with bit-flip swizzle: word q -> q ^ ((q>>5&1)<<2).
    #pragma unroll
    for (int k = 0; k < 2; k++) {
        int it = tid + k * 128;
        int q   = it & 63;
        int ocg = it >> 6;
        int Y   = q >> 2;
        int X   = q & 3;
        int o0 = (8 * X + 4 * (Y & 1)) & 31;
        int o1 = (o0 + 4) & 31;
        const uint32_t* row0 = P1 + 64 * Y;
        const uint32_t* row1 = row0 + 32;
        uint4 A0 = *(const uint4*)(row0 + o0);
        uint4 A1 = *(const uint4*)(row0 + o1);
        uint4 B0 = *(const uint4*)(row1 + o0);
        uint4 B1 = *(const uint4*)(row1 + o1);
        int ta[8] = {(int)A0.x,(int)A0.y,(int)A0.z,(int)A0.w,
                     (int)A1.x,(int)A1.y,(int)A1.z,(int)A1.w};
        int tb[8] = {(int)B0.x,(int)B0.y,(int)B0.z,(int)B0.w,
                     (int)B1.x,(int)B1.y,(int)B1.z,(int)B1.w};
        uint32_t* Dw = (uint32_t*)D;
        int qs = q ^ (((q >> 5) & 1) << 2);   // bit-flip swizzle
        #pragma unroll
        for (int oo = 0; oo < 8; oo++) {
            int oc = ocg * 8 + oo;
            int wv = (int)PW1w[oc];
            int m[4];
            #pragma unroll
            for (int j = 0; j < 4; j++) {
                int s0 = __dp4a(ta[2*j],     wv, 0);
                int s1 = __dp4a(ta[2*j + 1], wv, 0);
                int s2 = __dp4a(tb[2*j],     wv, 0);
                int s3 = __dp4a(tb[2*j + 1], wv, 0);
                m[j] = max(max(max(s0, s1), max(s2, s3)), 0);
            }
            Dw[oc * 64 + qs] = fq4x4(pack4(m[0], m[1], m[2], m[3]));
        }
    }

    // ---- wait for prep kernel (PDL): first use of the large packed weights ----
    cudaGridDependencySynchronize();

    // ---- stage large packed weights (L2-hot), vectorized, exact splits ----
    ((uint4*)PW2w)[tid] = ((const uint4*)gPW2)[tid];           // 128 exact
    #pragma unroll
    for (int k = 0; k < 4; k++)                                 // 512 = 4 exact
        ((uint4*)PW3w)[tid + k * 128] = ((const uint4*)gPW3)[tid + k * 128];
    if (tid < 96)  DW2r[tid] = gDW2r[tid];
    DW3r[tid] = gDW3r[tid];
    if (tid < 64) DW3r[tid + 128] = gDW3r[tid + 128];
    __syncthreads();

    // ---- dw2: depthwise 3x3, 32ch @16x16. Item = 8-px half-row of 1 ch.
    //      1024 items = 8 exact/thread. Bit-flip load swz; row-XOR store swz. ----
    #pragma unroll 4
    for (int k = 0; k < 8; k++) {
        int item = tid + k * 128;
        int c = item >> 5;
        int r = item & 31;
        int y = r >> 1, h = r & 1;
        const uint32_t* chb = (const uint32_t*)(D + c * 256);
        int acc[8] = {};
        #pragma unroll
        for (int ky = 0; ky < 3; ky++) {
            int yy = y + ky - 1;
            if ((unsigned)yy <= 15u) {
                int base = yy * 4;
                int xw = (yy & 8) >> 1;    // bit-flip swizzle
                uint32_t c0 = chb[(base + 2 * h) ^ xw];
                uint32_t c1 = chb[(base + 2 * h + 1) ^ xw];
                uint32_t lf = h ? chb[(base + 1) ^ xw] : 0u;
                uint32_t rt = h ? 0u : chb[(base + 2) ^ xw];
                int wv = (int)DW2r[c * 3 + ky];
                acc[0] = __dp4a((int)__byte_perm(c0, lf, 0x0107), wv, acc[0]);
                acc[1] = __dp4a((int)c0,                          wv, acc[1]);
                acc[2] = __dp4a((int)(c0 >> 8),                   wv, acc[2]);
                acc[3] = __dp4a((int)__byte_perm(c0, c1, 0x0432), wv, acc[3]);
                acc[4] = __dp4a((int)__byte_perm(c1, c0, 0x0107), wv, acc[4]);
                acc[5] = __dp4a((int)c1,                          wv, acc[5]);
                acc[6] = __dp4a((int)(c1 >> 8),                   wv, acc[6]);
                acc[7] = __dp4a((int)__byte_perm(c1, rt, 0x0432), wv, acc[7]);
            }
        }
        int g = c >> 2, ln = c & 3;
        int xmask = (((y >> 1) & 7) << 2) ^ ((g & 3) * 8);  // row-XOR + kgroup swizzle
        #pragma unroll
        for (int j = 0; j < 8; j++) {
            int xpix = h * 8 + j;
            int qidx = ((y >> 1) * 8 + (xpix >> 1)) * 4 + (y & 1) * 2 + (xpix & 1);
            ((signed char*)P2)[(g * 256 + (qidx ^ xmask)) * 4 + ln] =
                (signed char)clampi(rq2(acc[j]), -8, 7);
        }
    }
    __syncthreads();

    // ---- pw2 (32->64) via IMMA + relu + maxpool2 + requant ----
    // 8 warp-jobs over 4 warps = 2 exact/warp. Row-XOR read; chan-XOR store swz.
    {
        int warp = tid >> 5, lane = tid & 31;
        int li4 = lane >> 2, lm4 = lane & 3;
        int sw = lm4 * 8;
        #pragma unroll
        for (int jw = 0; jw < 2; jw++) {
            int w = warp + jw * 4;
            int m0 = (w & 3) * 16;
            int nh = w >> 2;
            int a0w = (int)PW2w[(m0 + li4) * 8 + lm4];
            int a1w = (int)PW2w[(m0 + li4 + 8) * 8 + lm4];
            int a2w = (int)PW2w[(m0 + li4) * 8 + 4 + lm4];
            int a3w = (int)PW2w[(m0 + li4 + 8) * 8 + 4 + lm4];
            #pragma unroll
            for (int t = 0; t < 16; t++) {
                int n0 = (nh * 16 + t) * 8;
                int nn = n0 + li4;
                int pxs = nn ^ (((nn >> 5) & 7) << 2) ^ sw;   // row-XOR swizzle
                int b0 = (int)P2[lm4 * 256 + pxs];
                int b1 = (int)P2[(4 + lm4) * 256 + pxs];
                int d0 = 0, d1 = 0, d2 = 0, d3 = 0;
                mma_s8(d0, d1, d2, d3, a0w, a1w, a2w, a3w, b0, b1);
                int mA = max(d0, d1);
                int mB = max(d2, d3);
                mA = max(mA, __shfl_xor_sync(0xffffffffu, mA, 1));
                mB = max(mB, __shfl_xor_sync(0xffffffffu, mB, 1));
                if (!(lane & 1)) {
                    int q = n0 / 4 + (lm4 >> 1);
                    int qs = ((((q >> 2) ^ li4) & 15) << 2) | (q & 3);  // chan-XOR swz
                    D3[(m0 + li4) * 64 + qs]     = (signed char)fq4(mA);
                    D3[(m0 + li4 + 8) * 64 + qs] = (signed char)fq4(mB);
                }
            }
        }
    }
    __syncthreads();

    // ---- dw3: depthwise 3x3, 64ch @8x8. Item = full 8-px row of 1 ch.
    //      512 items = 4 exact/thread. D3 loads apply channel-XOR swizzle. ----
    #pragma unroll
    for (int k = 0; k < 4; k++) {
        int item = tid + k * 128;
        int c = item >> 3;
        int y = item & 7;
        const uint32_t* chb = (const uint32_t*)D3 + c * 16;
        int xc = c & 7;                    // channel-XOR swizzle
        int acc[8] = {};
        #pragma unroll
        for (int ky = 0; ky < 3; ky++) {
            int yy = y + ky - 1;
            if ((unsigned)yy <= 7u) {
                uint32_t c0 = chb[(yy * 2) ^ xc];
                uint32_t c1 = chb[(yy * 2 + 1) ^ xc];
                int wv = (int)DW3r[c * 3 + ky];
                acc[0] = __dp4a((int)__byte_perm(c0, 0u, 0x0107), wv, acc[0]);
                acc[1] = __dp4a((int)c0,                          wv, acc[1]);
                acc[2] = __dp4a((int)(c0 >> 8),                   wv, acc[2]);
                acc[3] = __dp4a((int)__byte_perm(c0, c1, 0x0432), wv, acc[3]);
                acc[4] = __dp4a((int)__byte_perm(c1, c0, 0x0107), wv, acc[4]);
                acc[5] = __dp4a((int)c1,                          wv, acc[5]);
                acc[6] = __dp4a((int)(c1 >> 8),                   wv, acc[6]);
                acc[7] = __dp4a((int)__byte_perm(c1, 0u, 0x0432), wv, acc[7]);
            }
        }
        int g = c >> 2, ln = c & 3;
        int sw = (g & 3) * 8;
        #pragma unroll
        for (int j = 0; j < 8; j++) {
            int px = y * 8 + j;
            ((signed char*)P3)[(g * 64 + (px ^ sw)) * 4 + ln] =
                (signed char)clampi(rq2(acc[j]), -8, 7);
        }
    }
    __syncthreads();

    // ---- pw3 (64->128) via IMMA + global maxpool in registers -> Vb ----
    // 8 oc-tile jobs over 4 warps = 2 exact/warp.
    {
        int warp = tid >> 5, lane = tid & 31;
        int li4 = lane >> 2, lm4 = lane & 3;
        int sw = lm4 * 8;
        #pragma unroll
        for (int jw = 0; jw < 2; jw++) {
            int w = warp + jw * 4;
            int m0 = w * 16;
            int A[2][4];
            #pragma unroll
            for (int kt = 0; kt < 2; kt++) {
                A[kt][0] = (int)PW3w[(m0 + li4) * 16 + kt * 8 + lm4];
                A[kt][1] = (int)PW3w[(m0 + li4 + 8) * 16 + kt * 8 + lm4];
                A[kt][2] = (int)PW3w[(m0 + li4) * 16 + kt * 8 + 4 + lm4];
                A[kt][3] = (int)PW3w[(m0 + li4 + 8) * 16 + kt * 8 + 4 + lm4];
            }
            int mA = INT_MIN, mB = INT_MIN;
            #pragma unroll
            for (int t = 0; t < 8; t++) {
                int pxs = (t * 8 + li4) ^ sw;
                int d0 = 0, d1 = 0, d2 = 0, d3 = 0;
                #pragma unroll
                for (int kt = 0; kt < 2; kt++) {
                    int b0 = (int)P3[(kt * 8 + lm4) * 64 + pxs];
                    int b1 = (int)P3[(kt * 8 + 4 + lm4) * 64 + pxs];
                    mma_s8(d0, d1, d2, d3, A[kt][0], A[kt][1], A[kt][2], A[kt][3], b0, b1);
                }
                mA = max(mA, max(d0, d1));
                mB = max(mB, max(d2, d3));
            }
            mA = max(mA, __shfl_xor_sync(0xffffffffu, mA, 1));
            mA = max(mA, __shfl_xor_sync(0xffffffffu, mA, 2));
            mB = max(mB, __shfl_xor_sync(0xffffffffu, mB, 1));
            mB = max(mB, __shfl_xor_sync(0xffffffffu, mB, 2));
            if (lm4 == 0) {
                Vb[m0 + li4]     = (unsigned char)fq4(mA);
                Vb[m0 + li4 + 8] = (unsigned char)fq4(mB);
            }
        }
    }
    __syncthreads();

    // ---- fc1: 128->256 = 2 exact/thread (weights global, coalesced, L2-hot) ----
    #pragma unroll
    for (int k = 0; k < 2; k++) {
        int o = tid + k * 128;
        const uint32_t* Vw = (const uint32_t*)Vb;
        int S = 0;
        #pragma unroll 8
        for (int g = 0; g < 32; g++)
            S = __dp4a((int)Vw[g], (int)gFC1[g * 256 + o], S);
        V2b[o] = (unsigned char)fq4(S);
    }
    __syncthreads();

    // ---- fc2: 256->10 with 10 oc x 8 lanes, output int8 quant (2S trick) ----
    if (tid < 80) {
        int oc = tid >> 3, l = tid & 7;
        const uint32_t* Vw = (const uint32_t*)V2b;
        int S = 0;
        #pragma unroll
        for (int k = 0; k < 8; k++) {
            int g = l + k * 8;
            S = __dp4a((int)Vw[g], (int)gFC2[oc * 64 + g], S);
        }
        #pragma unroll
        for (int off = 4; off; off >>= 1) S += __shfl_down_sync(0xffffffffu, S, off, 8);
        if (l == 0) {
            int o = clampi(2 * S, -128, 127);
            out[(size_t)b * 10 + oc] = (float)o * 0.0625f;
        }
    }
}

extern "C" void kernel_launch(void* const* d_in, const int* in_sizes, int n_in,
                              void* d_out, int out_size)
{
    (void)in_sizes; (void)n_in; (void)out_size;
    const float* x   = (const float*)d_in[0];
    const float* w0  = (const float*)d_in[1];
    const float* dw1 = (const float*)d_in[2];
    const float* pw1 = (const float*)d_in[3];
    const float* dw2 = (const float*)d_in[4];
    const float* pw2 = (const float*)d_in[5];
    const float* dw3 = (const float*)d_in[6];
    const float* pw3 = (const float*)d_in[7];
    const float* wc1 = (const float*)d_in[8];
    const float* wc2 = (const float*)d_in[9];
    float* out = (float*)d_out;

    // Idempotent host-side config (safe under graph capture): allow max SMEM
    // carveout so 8 CTAs x 27968 B co-reside.
    cudaFuncSetAttribute(qnet_kernel, cudaFuncAttributePreferredSharedMemoryCarveout,
                         cudaSharedmemCarveoutMaxShared);

    prep_kernel<<<48, PTHREADS>>>(dw2, pw2, dw3, pw3, wc1, wc2);

    // qnet launched with Programmatic Stream Serialization: its CTAs begin
    // executing conv0/dw1/pw1 (per-CTA-quantized small weights) while prep
    // finishes; cudaGridDependencySynchronize() before dw2 orders the large
    // weight reads after prep's trigger.
    cudaLaunchConfig_t cfg = {};
    cfg.gridDim = dim3(1024, 1, 1);
    cfg.blockDim = dim3(QT, 1, 1);
    cfg.dynamicSmemBytes = SM_BYTES;
    cfg.stream = 0;
    cudaLaunchAttribute attrs[1];
    attrs[0].id = cudaLaunchAttributeProgrammaticStreamSerialization;
    attrs[0].val.programmaticStreamSerializationAllowed = 1;
    cfg.attrs = attrs;
    cfg.numAttrs = 1;
    cudaLaunchKernelEx(&cfg, qnet_kernel, x, out, w0, dw1, pw1);
}

// round 15
// speedup vs baseline: 1.1241x; 1.0596x over previous
#include <cuda_runtime.h>
#include <cstdint>

// Fully fused quantized CIFAR-10 net. Depthwise convs via dp4a (widened 8-px items),
// pointwise pw2/pw3 via IMMA mma.m16n8k32.s8 with register-resident pooling.
// Bank-conflict-free SMEM swizzles on D/P2/D3. PDL: qnet quantizes the small
// front-section weights itself and defers the grid dependency sync until after
// pw1, overlapping prep's execution with conv0+dw1+pw1. Bit-exact vs reference.
// 256 threads x 5 CTAs/SM (empirically optimal geometry).

#define THREADS 256

// ---------------- packed weight globals (written by prep_kernel) ----------------
__device__ __align__(16) uint32_t gPW2[512];   // pw2 [oc*8+g]: 4 ic codes
__device__ __align__(16) uint32_t gPW3[2048];  // pw3 [oc*16+g]: 4 ic codes
__device__ uint32_t gFC1[8192];  // fc1 [g*256+oc]: 4 ic codes (coalesced by oc)
__device__ uint32_t gFC2[640];   // fc2 [oc*64+g]: 4 ic codes
__device__ uint32_t gDW2r[96];   // dw2 row-packed [c*3+ky]
__device__ uint32_t gDW3r[192];  // dw3 row-packed [c*3+ky]

// ---------------- helpers ----------------
__device__ __forceinline__ int clampi(int v, int lo, int hi) { return min(max(v, lo), hi); }
__device__ __forceinline__ uint32_t pack4(int a, int b, int c, int d) {
    return (uint32_t)(a & 0xFF) | ((uint32_t)(b & 0xFF) << 8) |
           ((uint32_t)(c & 0xFF) << 16) | ((uint32_t)(d & 0xFF) << 24);
}
__device__ __forceinline__ int qw4c(float w) {
    float q = rintf(w * 4.f); return (int)fmaxf(-8.f, fminf(7.f, q));
}
__device__ __forceinline__ int qw8c(float w) {
    float q = rintf(w * 4.f); return (int)fmaxf(-128.f, fminf(127.f, q));
}
__device__ __forceinline__ int qa8c(float v) {
    return clampi(__float2int_rn(v * 16.f), -128, 127);
}
// branch-free round-half-even of S/4
__device__ __forceinline__ int rq2(int S) {
    return (S + 1 + ((S >> 2) & 1)) >> 2;
}
// branch-free round-half-even of S/32
__device__ __forceinline__ int rq5(int S) {
    return (S + 15 + ((S >> 5) & 1)) >> 5;
}
// fused QuantReLU4 + S_ACT4 requant
__device__ __forceinline__ int fq4(int S) {
    int m = max(S, 0);
    return min((m + 1 + ((m >> 2) & 1)) >> 2, 7);
}
// packed fq4 on 4 unsigned bytes (values in [0,252])
__device__ __forceinline__ uint32_t fq4x4(uint32_t p) {
    uint32_t inc = ((p >> 2) & 0x01010101u) + 0x01010101u;
    uint32_t t = __vadd4(p, inc);
    return __vminu4((t >> 2) & 0x3F3F3F3Fu, 0x07070707u);
}
// s8 tensor-core mma, D += A*B (s32 accumulate)
__device__ __forceinline__ void mma_s8(int& d0, int& d1, int& d2, int& d3,
                                       int a0, int a1, int a2, int a3,
                                       int b0, int b1) {
    asm volatile("mma.sync.aligned.m16n8k32.row.col.s32.s8.s8.s32 "
                 "{%0,%1,%2,%3}, {%4,%5,%6,%7}, {%8,%9}, {%0,%1,%2,%3};"
                 : "+r"(d0), "+r"(d1), "+r"(d2), "+r"(d3)
                 : "r"(a0), "r"(a1), "r"(a2), "r"(a3), "r"(b0), "r"(b1));
}

// ---------------- prep: quantize + pack the large weights ----------------
__global__ void prep_kernel(const float* __restrict__ dw2,
                            const float* __restrict__ pw2, const float* __restrict__ dw3,
                            const float* __restrict__ pw3, const float* __restrict__ wc1,
                            const float* __restrict__ wc2)
{
    int t = blockIdx.x * blockDim.x + threadIdx.x;
    int NT = gridDim.x * blockDim.x;
    for (int i = t; i < 512; i += NT) {
        int oc = i >> 3, g = i & 7; const float* p = pw2 + oc*32 + g*4;
        gPW2[i] = pack4(qw4c(p[0]), qw4c(p[1]), qw4c(p[2]), qw4c(p[3]));
    }
    for (int i = t; i < 2048; i += NT) {
        int oc = i >> 4, g = i & 15; const float* p = pw3 + oc*64 + g*4;
        gPW3[i] = pack4(qw4c(p[0]), qw4c(p[1]), qw4c(p[2]), qw4c(p[3]));
    }
    for (int i = t; i < 8192; i += NT) {
        int g = i >> 8, oc = i & 255; const float* p = wc1 + oc*128 + g*4;
        gFC1[i] = pack4(qw4c(p[0]), qw4c(p[1]), qw4c(p[2]), qw4c(p[3]));
    }
    for (int i = t; i < 640; i += NT) {
        int oc = i / 64, g = i & 63; const float* p = wc2 + oc*256 + g*4;
        gFC2[i] = pack4(qw4c(p[0]), qw4c(p[1]), qw4c(p[2]), qw4c(p[3]));
    }
    for (int i = t; i < 96; i += NT) {
        int c = i / 3, ky = i % 3; const float* p = dw2 + c*9 + ky*3;
        gDW2r[i] = pack4(qw4c(p[0]), qw4c(p[1]), qw4c(p[2]), 0);
    }
    for (int i = t; i < 192; i += NT) {
        int c = i / 3, ky = i % 3; const float* p = dw3 + c*9 + ky*3;
        gDW3r[i] = pack4(qw4c(p[0]), qw4c(p[1]), qw4c(p[2]), 0);
    }
    cudaTriggerProgrammaticLaunchCompletion();
}

// ---------------- main fused kernel ----------------
// SMEM (27968 B): R0 [0,8192) / R1 [8192,16384) alternate stage buffers.
//  PW2w [16384,18432) PW3w [18432,26624) PW1w [26624,26752)
//  DW1r [26752,26792) DW2r [26792,27176) DW3r [27176,27944) W0w [27944,27960)
#define SM_BYTES 27968

__global__ __launch_bounds__(THREADS, 5)
void qnet_kernel(const float* __restrict__ x, float* __restrict__ out,
                 const float* __restrict__ w0f, const float* __restrict__ dw1f,
                 const float* __restrict__ pw1f)
{
    extern __shared__ unsigned char sm[];
    const int tid = threadIdx.x;
    const int b   = blockIdx.x;

    signed char*   B    = (signed char*)(sm);           // conv0 out [c][1024], x-packed
    uint32_t*      P1   = (uint32_t*)(sm + 8192);       // dw1 out, rotated rows
    signed char*   D    = (signed char*)(sm);           // pw1 out [oc][256], bit-flip swz
    uint32_t*      P2   = (uint32_t*)(sm + 8192);       // dw2 out [g][qidx'] row-XOR swz
    signed char*   D3   = (signed char*)(sm);           // pw2 out [oc][64], chan-XOR swz
    uint32_t*      P3   = (uint32_t*)(sm + 8192);       // dw3 out [g][px^sw] 4ch words
    unsigned char* Vb   = (unsigned char*)(sm);         // 128 (R0; D3 dead by then)
    unsigned char* V2b  = (unsigned char*)(sm + 256);   // 256
    uint32_t*      PW2w = (uint32_t*)(sm + 16384);
    uint32_t*      PW3w = (uint32_t*)(sm + 18432);
    uint32_t*      PW1w = (uint32_t*)(sm + 26624);
    uint32_t*      DW1r = (uint32_t*)(sm + 26752);
    uint32_t*      DW2r = (uint32_t*)(sm + 26792);
    uint32_t*      DW3r = (uint32_t*)(sm + 27176);
    uint32_t*      W0w  = (uint32_t*)(sm + 27944);

    // ---- input loads + quant/pack AND per-CTA small-weight quantization ----
    // (everything here is independent of prep_kernel's output)
    const float4* xv = (const float4*)(x + (size_t)b * 3072);
    float4 v0 = xv[tid];          // channel 0, px 4t..4t+3
    float4 v1 = xv[256 + tid];    // channel 1
    float4 v2 = xv[512 + tid];    // channel 2
    if (tid < 3) {
        const float* p = w0f + tid * 3;
        W0w[tid] = pack4(qw8c(p[0]), qw8c(p[1]), qw8c(p[2]), 0);
    } else if (tid >= 4 && tid < 13) {
        int i = tid - 4;                   // dw1 row-packed [c*3+ky]
        const float* p = dw1f + i * 3;
        DW1r[i] = pack4(qw4c(p[0]), qw4c(p[1]), qw4c(p[2]), 0);
    } else if (tid >= 64 && tid < 96) {
        int oc = tid - 64;
        const float* p = pw1f + oc * 3;
        PW1w[oc] = pack4(qw4c(p[0]), qw4c(p[1]), qw4c(p[2]), 0);
    }
    int a0 = (int)pack4(qa8c(v0.x), qa8c(v1.x), qa8c(v2.x), 0);
    int a1 = (int)pack4(qa8c(v0.y), qa8c(v1.y), qa8c(v2.y), 0);
    int a2 = (int)pack4(qa8c(v0.z), qa8c(v1.z), qa8c(v2.z), 0);
    int a3 = (int)pack4(qa8c(v0.w), qa8c(v1.w), qa8c(v2.w), 0);
    __syncthreads();

    // ---- conv0 (1x1, 3->3) + act4 requant ----
    {
        #pragma unroll
        for (int oc = 0; oc < 3; oc++) {
            int wv = (int)W0w[oc];
            int c0 = clampi(rq5(__dp4a(a0, wv, 0)), -8, 7);
            int c1 = clampi(rq5(__dp4a(a1, wv, 0)), -8, 7);
            int c2 = clampi(rq5(__dp4a(a2, wv, 0)), -8, 7);
            int c3 = clampi(rq5(__dp4a(a3, wv, 0)), -8, 7);
            ((uint32_t*)B)[oc * 256 + tid] = pack4(c0, c1, c2, c3);
        }
    }
    __syncthreads();

    // ---- dw1: depthwise 3x3, 3ch @32x32. Thread = 1 word (4 px), all 3 ch.
    //      P1 rows rotated by 4*((y>>1)&1) words (bank-conflict-free pw1 loads). ----
    {
        int y = tid >> 3, wx = tid & 7;
        int res[3][4];
        #pragma unroll
        for (int c = 0; c < 3; c++) {
            int s0 = 0, s1 = 0, s2 = 0, s3 = 0;
            #pragma unroll
            for (int ky = 0; ky < 3; ky++) {
                int yy = y + ky - 1;
                if ((unsigned)yy <= 31u) {
                    const uint32_t* rp = (const uint32_t*)(B + c * 1024 + yy * 32);
                    uint32_t cur  = rp[wx];
                    uint32_t prev = wx ? rp[wx - 1] : 0u;
                    uint32_t nxt  = (wx < 7) ? rp[wx + 1] : 0u;
                    int wv = (int)DW1r[c * 3 + ky];
                    s0 = __dp4a((int)__byte_perm(cur, prev, 0x0107), wv, s0);
                    s1 = __dp4a((int)cur,                            wv, s1);
                    s2 = __dp4a((int)(cur >> 8),                     wv, s2);
                    s3 = __dp4a((int)__byte_perm(cur, nxt, 0x0432),  wv, s3);
                }
            }
            res[c][0] = clampi(rq2(s0), -8, 7);
            res[c][1] = clampi(rq2(s1), -8, 7);
            res[c][2] = clampi(rq2(s2), -8, 7);
            res[c][3] = clampi(rq2(s3), -8, 7);
        }
        uint4 o;
        o.x = pack4(res[0][0], res[1][0], res[2][0], 0);
        o.y = pack4(res[0][1], res[1][1], res[2][1], 0);
        o.z = pack4(res[0][2], res[1][2], res[2][2], 0);
        o.w = pack4(res[0][3], res[1][3], res[2][3], 0);
        int off = (wx * 4 + ((y >> 1) & 1) * 4) & 31;   // row rotation
        *(uint4*)(P1 + y * 32 + off) = o;
    }
    __syncthreads();

    // ---- pw1 (3->32) + relu + maxpool2 + act4 requant ----
    // Thread = (8 oc) x (4 pooled px). Rotated loads (conflict-free LDS.128).
    // D stored with bit-flip swizzle: word q -> q ^ ((q>>5&1)<<2).
    {
        int q   = tid & 63;
        int ocg = tid >> 6;
        int Y   = q >> 2;
        int X   = q & 3;
        int o0 = (8 * X + 4 * (Y & 1)) & 31;
        int o1 = (o0 + 4) & 31;
        const uint32_t* row0 = P1 + 64 * Y;
        const uint32_t* row1 = row0 + 32;
        uint4 A0 = *(const uint4*)(row0 + o0);
        uint4 A1 = *(const uint4*)(row0 + o1);
        uint4 B0 = *(const uint4*)(row1 + o0);
        uint4 B1 = *(const uint4*)(row1 + o1);
        int ta[8] = {(int)A0.x,(int)A0.y,(int)A0.z,(int)A0.w,
                     (int)A1.x,(int)A1.y,(int)A1.z,(int)A1.w};
        int tb[8] = {(int)B0.x,(int)B0.y,(int)B0.z,(int)B0.w,
                     (int)B1.x,(int)B1.y,(int)B1.z,(int)B1.w};
        uint32_t* Dw = (uint32_t*)D;
        int qs = q ^ (((q >> 5) & 1) << 2);   // bit-flip swizzle
        #pragma unroll
        for (int oo = 0; oo < 8; oo++) {
            int oc = ocg * 8 + oo;
            int wv = (int)PW1w[oc];
            int m[4];
            #pragma unroll
            for (int j = 0; j < 4; j++) {
                int s0 = __dp4a(ta[2*j],     wv, 0);
                int s1 = __dp4a(ta[2*j + 1], wv, 0);
                int s2 = __dp4a(tb[2*j],     wv, 0);
                int s3 = __dp4a(tb[2*j + 1], wv, 0);
                m[j] = max(max(max(s0, s1), max(s2, s3)), 0);
            }
            Dw[oc * 64 + qs] = fq4x4(pack4(m[0], m[1], m[2], m[3]));
        }
    }

    // ---- wait for prep kernel (PDL): first use of the large packed weights ----
    cudaGridDependencySynchronize();

    // ---- stage large packed weights (L2-hot), vectorized ----
    if (tid < 128) ((uint4*)PW2w)[tid] = ((const uint4*)gPW2)[tid];
    ((uint4*)PW3w)[tid]       = ((const uint4*)gPW3)[tid];
    ((uint4*)PW3w)[tid + 256] = ((const uint4*)gPW3)[tid + 256];
    if (tid < 96)  DW2r[tid] = gDW2r[tid];
    if (tid < 192) DW3r[tid] = gDW3r[tid];
    __syncthreads();

    // ---- dw2: depthwise 3x3, 32ch @16x16. Item = 8-px half-row of 1 ch.
    //      D loads use bit-flip swizzle; P2 stores use row-XOR swizzle. ----
    #pragma unroll
    for (int k = 0; k < 4; k++) {
        int item = tid + k * 256;          // 0..1023
        int c = item >> 5;
        int r = item & 31;
        int y = r >> 1, h = r & 1;
        const uint32_t* chb = (const uint32_t*)(D + c * 256);
        int acc[8] = {};
        #pragma unroll
        for (int ky = 0; ky < 3; ky++) {
            int yy = y + ky - 1;
            if ((unsigned)yy <= 15u) {
                int base = yy * 4;
                int xw = (yy & 8) >> 1;    // bit-flip swizzle
                uint32_t c0 = chb[(base + 2 * h) ^ xw];
                uint32_t c1 = chb[(base + 2 * h + 1) ^ xw];
                uint32_t lf = h ? chb[(base + 1) ^ xw] : 0u;
                uint32_t rt = h ? 0u : chb[(base + 2) ^ xw];
                int wv = (int)DW2r[c * 3 + ky];
                acc[0] = __dp4a((int)__byte_perm(c0, lf, 0x0107), wv, acc[0]);
                acc[1] = __dp4a((int)c0,                          wv, acc[1]);
                acc[2] = __dp4a((int)(c0 >> 8),                   wv, acc[2]);
                acc[3] = __dp4a((int)__byte_perm(c0, c1, 0x0432), wv, acc[3]);
                acc[4] = __dp4a((int)__byte_perm(c1, c0, 0x0107), wv, acc[4]);
                acc[5] = __dp4a((int)c1,                          wv, acc[5]);
                acc[6] = __dp4a((int)(c1 >> 8),                   wv, acc[6]);
                acc[7] = __dp4a((int)__byte_perm(c1, rt, 0x0432), wv, acc[7]);
            }
        }
        int g = c >> 2, ln = c & 3;
        int xmask = (((y >> 1) & 7) << 2) ^ ((g & 3) * 8);  // row-XOR + kgroup swizzle
        #pragma unroll
        for (int j = 0; j < 8; j++) {
            int xpix = h * 8 + j;
            int qidx = ((y >> 1) * 8 + (xpix >> 1)) * 4 + (y & 1) * 2 + (xpix & 1);
            ((signed char*)P2)[(g * 256 + (qidx ^ xmask)) * 4 + ln] =
                (signed char)clampi(rq2(acc[j]), -8, 7);
        }
    }
    __syncthreads();

    // ---- pw2 (32->64) via IMMA + relu + maxpool2 + requant ----
    // P2 read applies row-XOR swizzle; D3 store applies channel-XOR swizzle.
    {
        int w = tid >> 5, lane = tid & 31;
        int li4 = lane >> 2, lm4 = lane & 3;
        int m0 = (w & 3) * 16;
        int nh = w >> 2;
        int a0w = (int)PW2w[(m0 + li4) * 8 + lm4];
        int a1w = (int)PW2w[(m0 + li4 + 8) * 8 + lm4];
        int a2w = (int)PW2w[(m0 + li4) * 8 + 4 + lm4];
        int a3w = (int)PW2w[(m0 + li4 + 8) * 8 + 4 + lm4];
        int sw = lm4 * 8;
        #pragma unroll
        for (int t = 0; t < 16; t++) {
            int n0 = (nh * 16 + t) * 8;
            int nn = n0 + li4;
            int pxs = nn ^ (((nn >> 5) & 7) << 2) ^ sw;   // row-XOR swizzle
            int b0 = (int)P2[lm4 * 256 + pxs];
            int b1 = (int)P2[(4 + lm4) * 256 + pxs];
            int d0 = 0, d1 = 0, d2 = 0, d3 = 0;
            mma_s8(d0, d1, d2, d3, a0w, a1w, a2w, a3w, b0, b1);
            int mA = max(d0, d1);
            int mB = max(d2, d3);
            mA = max(mA, __shfl_xor_sync(0xffffffffu, mA, 1));
            mB = max(mB, __shfl_xor_sync(0xffffffffu, mB, 1));
            if (!(lane & 1)) {
                int q = n0 / 4 + (lm4 >> 1);
                int qs = ((((q >> 2) ^ li4) & 15) << 2) | (q & 3);  // chan-XOR swizzle
                D3[(m0 + li4) * 64 + qs]     = (signed char)fq4(mA);
                D3[(m0 + li4 + 8) * 64 + qs] = (signed char)fq4(mB);
            }
        }
    }
    __syncthreads();

    // ---- dw3: depthwise 3x3, 64ch @8x8. Item = full 8-px row of 1 ch.
    //      D3 loads apply channel-XOR swizzle. ----
    #pragma unroll
    for (int k = 0; k < 2; k++) {
        int item = tid + k * 256;          // 0..511
        int c = item >> 3;
        int y = item & 7;
        const uint32_t* chb = (const uint32_t*)D3 + c * 16;
        int xc = c & 7;                    // channel-XOR swizzle
        int acc[8] = {};
        #pragma unroll
        for (int ky = 0; ky < 3; ky++) {
            int yy = y + ky - 1;
            if ((unsigned)yy <= 7u) {
                uint32_t c0 = chb[(yy * 2) ^ xc];
                uint32_t c1 = chb[(yy * 2 + 1) ^ xc];
                int wv = (int)DW3r[c * 3 + ky];
                acc[0] = __dp4a((int)__byte_perm(c0, 0u, 0x0107), wv, acc[0]);
                acc[1] = __dp4a((int)c0,                          wv, acc[1]);
                acc[2] = __dp4a((int)(c0 >> 8),                   wv, acc[2]);
                acc[3] = __dp4a((int)__byte_perm(c0, c1, 0x0432), wv, acc[3]);
                acc[4] = __dp4a((int)__byte_perm(c1, c0, 0x0107), wv, acc[4]);
                acc[5] = __dp4a((int)c1,                          wv, acc[5]);
                acc[6] = __dp4a((int)(c1 >> 8),                   wv, acc[6]);
                acc[7] = __dp4a((int)__byte_perm(c1, 0u, 0x0432), wv, acc[7]);
            }
        }
        int g = c >> 2, ln = c & 3;
        int sw = (g & 3) * 8;
        #pragma unroll
        for (int j = 0; j < 8; j++) {
            int px = y * 8 + j;
            ((signed char*)P3)[(g * 64 + (px ^ sw)) * 4 + ln] =
                (signed char)clampi(rq2(acc[j]), -8, 7);
        }
    }
    __syncthreads();

    // ---- pw3 (64->128) via IMMA + global maxpool in registers -> Vb ----
    {
        int w = tid >> 5, lane = tid & 31;
        int li4 = lane >> 2, lm4 = lane & 3;
        int m0 = w * 16;
        int A[2][4];
        #pragma unroll
        for (int kt = 0; kt < 2; kt++) {
            A[kt][0] = (int)PW3w[(m0 + li4) * 16 + kt * 8 + lm4];
            A[kt][1] = (int)PW3w[(m0 + li4 + 8) * 16 + kt * 8 + lm4];
            A[kt][2] = (int)PW3w[(m0 + li4) * 16 + kt * 8 + 4 + lm4];
            A[kt][3] = (int)PW3w[(m0 + li4 + 8) * 16 + kt * 8 + 4 + lm4];
        }
        int sw = lm4 * 8;
        int mA = INT_MIN, mB = INT_MIN;
        #pragma unroll
        for (int t = 0; t < 8; t++) {
            int pxs = (t * 8 + li4) ^ sw;
            int d0 = 0, d1 = 0, d2 = 0, d3 = 0;
            #pragma unroll
            for (int kt = 0; kt < 2; kt++) {
                int b0 = (int)P3[(kt * 8 + lm4) * 64 + pxs];
                int b1 = (int)P3[(kt * 8 + 4 + lm4) * 64 + pxs];
                mma_s8(d0, d1, d2, d3, A[kt][0], A[kt][1], A[kt][2], A[kt][3], b0, b1);
            }
            mA = max(mA, max(d0, d1));
            mB = max(mB, max(d2, d3));
        }
        mA = max(mA, __shfl_xor_sync(0xffffffffu, mA, 1));
        mA = max(mA, __shfl_xor_sync(0xffffffffu, mA, 2));
        mB = max(mB, __shfl_xor_sync(0xffffffffu, mB, 1));
        mB = max(mB, __shfl_xor_sync(0xffffffffu, mB, 2));
        if (lm4 == 0) {
            Vb[m0 + li4]     = (unsigned char)fq4(mA);
            Vb[m0 + li4 + 8] = (unsigned char)fq4(mB);
        }
    }
    __syncthreads();

    // ---- fc1: 128->256 (weights streamed from global, coalesced, L2-hot) ----
    {
        const uint32_t* Vw = (const uint32_t*)Vb;
        int S = 0;
        #pragma unroll 8
        for (int g = 0; g < 32; g++)
            S = __dp4a((int)Vw[g], (int)gFC1[g * 256 + tid], S);
        V2b[tid] = (unsigned char)fq4(S);
    }
    __syncthreads();

    // ---- fc2: 256->10 with 10 oc x 8 lanes; output int8 quant (2S trick) ----
    if (tid < 80) {
        int oc = tid >> 3, l = tid & 7;
        const uint32_t* Vw = (const uint32_t*)V2b;
        int S = 0;
        #pragma unroll
        for (int k = 0; k < 8; k++) {
            int g = l + k * 8;
            S = __dp4a((int)Vw[g], (int)gFC2[oc * 64 + g], S);
        }
        #pragma unroll
        for (int off = 4; off; off >>= 1) S += __shfl_down_sync(0xffffffffu, S, off, 8);
        if (l == 0) {
            int o = clampi(2 * S, -128, 127);
            out[(size_t)b * 10 + oc] = (float)o * 0.0625f;
        }
    }
}

extern "C" void kernel_launch(void* const* d_in, const int* in_sizes, int n_in,
                              void* d_out, int out_size)
{
    (void)in_sizes; (void)n_in; (void)out_size;
    const float* x   = (const float*)d_in[0];
    const float* w0  = (const float*)d_in[1];
    const float* dw1 = (const float*)d_in[2];
    const float* pw1 = (const float*)d_in[3];
    const float* dw2 = (const float*)d_in[4];
    const float* pw2 = (const float*)d_in[5];
    const float* dw3 = (const float*)d_in[6];
    const float* pw3 = (const float*)d_in[7];
    const float* wc1 = (const float*)d_in[8];
    const float* wc2 = (const float*)d_in[9];
    float* out = (float*)d_out;

    prep_kernel<<<148, THREADS>>>(dw2, pw2, dw3, pw3, wc1, wc2);

    // qnet launched with Programmatic Stream Serialization: its CTAs begin
    // executing conv0/dw1/pw1 (per-CTA-quantized small weights) while prep
    // finishes; cudaGridDependencySynchronize() before dw2 orders the large
    // weight reads after prep's trigger.
    cudaLaunchConfig_t cfg = {};
    cfg.gridDim = dim3(1024, 1, 1);
    cfg.blockDim = dim3(THREADS, 1, 1);
    cfg.dynamicSmemBytes = SM_BYTES;
    cfg.stream = 0;
    cudaLaunchAttribute attrs[1];
    attrs[0].id = cudaLaunchAttributeProgrammaticStreamSerialization;
    attrs[0].val.programmaticStreamSerializationAllowed = 1;
    cfg.attrs = attrs;
    cfg.numAttrs = 1;
    cudaLaunchKernelEx(&cfg, qnet_kernel, x, out, w0, dw1, pw1);
}

// round 16
// speedup vs baseline: 1.1635x; 1.0351x over previous
#include <cuda_runtime.h>
#include <cstdint>

// Fully fused quantized CIFAR-10 net. Depthwise convs via dp4a (widened 8-px items),
// pointwise pw2/pw3 via IMMA mma.m16n8k32.s8 with register-resident pooling.
// Bank-conflict-free SMEM swizzles on D/P2/D3. PDL: qnet quantizes the small
// front-section weights itself and defers the grid dependency sync until after
// pw1, overlapping prep's execution with conv0+dw1+pw1. Bit-exact vs reference.
// 256 threads x 5 CTAs/SM; prep at 48 CTAs (minimal interference under PDL).

#define THREADS 256

// ---------------- packed weight globals (written by prep_kernel) ----------------
__device__ __align__(16) uint32_t gPW2[512];   // pw2 [oc*8+g]: 4 ic codes
__device__ __align__(16) uint32_t gPW3[2048];  // pw3 [oc*16+g]: 4 ic codes
__device__ uint32_t gFC1[8192];  // fc1 [g*256+oc]: 4 ic codes (coalesced by oc)
__device__ uint32_t gFC2[640];   // fc2 [oc*64+g]: 4 ic codes
__device__ uint32_t gDW2r[96];   // dw2 row-packed [c*3+ky]
__device__ uint32_t gDW3r[192];  // dw3 row-packed [c*3+ky]

// ---------------- helpers ----------------
__device__ __forceinline__ int clampi(int v, int lo, int hi) { return min(max(v, lo), hi); }
__device__ __forceinline__ uint32_t pack4(int a, int b, int c, int d) {
    return (uint32_t)(a & 0xFF) | ((uint32_t)(b & 0xFF) << 8) |
           ((uint32_t)(c & 0xFF) << 16) | ((uint32_t)(d & 0xFF) << 24);
}
__device__ __forceinline__ int qw4c(float w) {
    float q = rintf(w * 4.f); return (int)fmaxf(-8.f, fminf(7.f, q));
}
__device__ __forceinline__ int qw8c(float w) {
    float q = rintf(w * 4.f); return (int)fmaxf(-128.f, fminf(127.f, q));
}
__device__ __forceinline__ int qa8c(float v) {
    return clampi(__float2int_rn(v * 16.f), -128, 127);
}
// branch-free round-half-even of S/4
__device__ __forceinline__ int rq2(int S) {
    return (S + 1 + ((S >> 2) & 1)) >> 2;
}
// branch-free round-half-even of S/32
__device__ __forceinline__ int rq5(int S) {
    return (S + 15 + ((S >> 5) & 1)) >> 5;
}
// fused QuantReLU4 + S_ACT4 requant
__device__ __forceinline__ int fq4(int S) {
    int m = max(S, 0);
    return min((m + 1 + ((m >> 2) & 1)) >> 2, 7);
}
// packed fq4 on 4 unsigned bytes (values in [0,252])
__device__ __forceinline__ uint32_t fq4x4(uint32_t p) {
    uint32_t inc = ((p >> 2) & 0x01010101u) + 0x01010101u;
    uint32_t t = __vadd4(p, inc);
    return __vminu4((t >> 2) & 0x3F3F3F3Fu, 0x07070707u);
}
// s8 tensor-core mma, D += A*B (s32 accumulate)
__device__ __forceinline__ void mma_s8(int& d0, int& d1, int& d2, int& d3,
                                       int a0, int a1, int a2, int a3,
                                       int b0, int b1) {
    asm volatile("mma.sync.aligned.m16n8k32.row.col.s32.s8.s8.s32 "
                 "{%0,%1,%2,%3}, {%4,%5,%6,%7}, {%8,%9}, {%0,%1,%2,%3};"
                 : "+r"(d0), "+r"(d1), "+r"(d2), "+r"(d3)
                 : "r"(a0), "r"(a1), "r"(a2), "r"(a3), "r"(b0), "r"(b1));
}

// ---------------- prep: quantize + pack the large weights ----------------
__global__ void prep_kernel(const float* __restrict__ dw2,
                            const float* __restrict__ pw2, const float* __restrict__ dw3,
                            const float* __restrict__ pw3, const float* __restrict__ wc1,
                            const float* __restrict__ wc2)
{
    int t = blockIdx.x * blockDim.x + threadIdx.x;
    int NT = gridDim.x * blockDim.x;
    for (int i = t; i < 512; i += NT) {
        int oc = i >> 3, g = i & 7; const float* p = pw2 + oc*32 + g*4;
        gPW2[i] = pack4(qw4c(p[0]), qw4c(p[1]), qw4c(p[2]), qw4c(p[3]));
    }
    for (int i = t; i < 2048; i += NT) {
        int oc = i >> 4, g = i & 15; const float* p = pw3 + oc*64 + g*4;
        gPW3[i] = pack4(qw4c(p[0]), qw4c(p[1]), qw4c(p[2]), qw4c(p[3]));
    }
    for (int i = t; i < 8192; i += NT) {
        int g = i >> 8, oc = i & 255; const float* p = wc1 + oc*128 + g*4;
        gFC1[i] = pack4(qw4c(p[0]), qw4c(p[1]), qw4c(p[2]), qw4c(p[3]));
    }
    for (int i = t; i < 640; i += NT) {
        int oc = i / 64, g = i & 63; const float* p = wc2 + oc*256 + g*4;
        gFC2[i] = pack4(qw4c(p[0]), qw4c(p[1]), qw4c(p[2]), qw4c(p[3]));
    }
    for (int i = t; i < 96; i += NT) {
        int c = i / 3, ky = i % 3; const float* p = dw2 + c*9 + ky*3;
        gDW2r[i] = pack4(qw4c(p[0]), qw4c(p[1]), qw4c(p[2]), 0);
    }
    for (int i = t; i < 192; i += NT) {
        int c = i / 3, ky = i % 3; const float* p = dw3 + c*9 + ky*3;
        gDW3r[i] = pack4(qw4c(p[0]), qw4c(p[1]), qw4c(p[2]), 0);
    }
    cudaTriggerProgrammaticLaunchCompletion();
}

// ---------------- main fused kernel ----------------
// SMEM (27968 B): R0 [0,8192) / R1 [8192,16384) alternate stage buffers.
//  PW2w [16384,18432) PW3w [18432,26624) PW1w [26624,26752)
//  DW1r [26752,26792) DW2r [26792,27176) DW3r [27176,27944) W0w [27944,27960)
#define SM_BYTES 27968

__global__ __launch_bounds__(THREADS, 5)
void qnet_kernel(const float* __restrict__ x, float* __restrict__ out,
                 const float* __restrict__ w0f, const float* __restrict__ dw1f,
                 const float* __restrict__ pw1f)
{
    extern __shared__ unsigned char sm[];
    const int tid = threadIdx.x;
    const int b   = blockIdx.x;

    signed char*   B    = (signed char*)(sm);           // conv0 out [c][1024], x-packed
    uint32_t*      P1   = (uint32_t*)(sm + 8192);       // dw1 out, rotated rows
    signed char*   D    = (signed char*)(sm);           // pw1 out [oc][256], bit-flip swz
    uint32_t*      P2   = (uint32_t*)(sm + 8192);       // dw2 out [g][qidx'] row-XOR swz
    signed char*   D3   = (signed char*)(sm);           // pw2 out [oc][64], chan-XOR swz
    uint32_t*      P3   = (uint32_t*)(sm + 8192);       // dw3 out [g][px^sw] 4ch words
    unsigned char* Vb   = (unsigned char*)(sm);         // 128 (R0; D3 dead by then)
    unsigned char* V2b  = (unsigned char*)(sm + 256);   // 256
    uint32_t*      PW2w = (uint32_t*)(sm + 16384);
    uint32_t*      PW3w = (uint32_t*)(sm + 18432);
    uint32_t*      PW1w = (uint32_t*)(sm + 26624);
    uint32_t*      DW1r = (uint32_t*)(sm + 26752);
    uint32_t*      DW2r = (uint32_t*)(sm + 26792);
    uint32_t*      DW3r = (uint32_t*)(sm + 27176);
    uint32_t*      W0w  = (uint32_t*)(sm + 27944);

    // ---- input loads + quant/pack AND per-CTA small-weight quantization ----
    // (everything here is independent of prep_kernel's output)
    const float4* xv = (const float4*)(x + (size_t)b * 3072);
    float4 v0 = xv[tid];          // channel 0, px 4t..4t+3
    float4 v1 = xv[256 + tid];    // channel 1
    float4 v2 = xv[512 + tid];    // channel 2
    if (tid < 3) {
        const float* p = w0f + tid * 3;
        W0w[tid] = pack4(qw8c(p[0]), qw8c(p[1]), qw8c(p[2]), 0);
    } else if (tid >= 4 && tid < 13) {
        int i = tid - 4;                   // dw1 row-packed [c*3+ky]
        const float* p = dw1f + i * 3;
        DW1r[i] = pack4(qw4c(p[0]), qw4c(p[1]), qw4c(p[2]), 0);
    } else if (tid >= 64 && tid < 96) {
        int oc = tid - 64;
        const float* p = pw1f + oc * 3;
        PW1w[oc] = pack4(qw4c(p[0]), qw4c(p[1]), qw4c(p[2]), 0);
    }
    int a0 = (int)pack4(qa8c(v0.x), qa8c(v1.x), qa8c(v2.x), 0);
    int a1 = (int)pack4(qa8c(v0.y), qa8c(v1.y), qa8c(v2.y), 0);
    int a2 = (int)pack4(qa8c(v0.z), qa8c(v1.z), qa8c(v2.z), 0);
    int a3 = (int)pack4(qa8c(v0.w), qa8c(v1.w), qa8c(v2.w), 0);
    __syncthreads();

    // ---- conv0 (1x1, 3->3) + act4 requant ----
    {
        #pragma unroll
        for (int oc = 0; oc < 3; oc++) {
            int wv = (int)W0w[oc];
            int c0 = clampi(rq5(__dp4a(a0, wv, 0)), -8, 7);
            int c1 = clampi(rq5(__dp4a(a1, wv, 0)), -8, 7);
            int c2 = clampi(rq5(__dp4a(a2, wv, 0)), -8, 7);
            int c3 = clampi(rq5(__dp4a(a3, wv, 0)), -8, 7);
            ((uint32_t*)B)[oc * 256 + tid] = pack4(c0, c1, c2, c3);
        }
    }
    __syncthreads();

    // ---- dw1: depthwise 3x3, 3ch @32x32. Thread = 1 word (4 px), all 3 ch.
    //      P1 rows rotated by 4*((y>>1)&1) words (bank-conflict-free pw1 loads). ----
    {
        int y = tid >> 3, wx = tid & 7;
        int res[3][4];
        #pragma unroll
        for (int c = 0; c < 3; c++) {
            int s0 = 0, s1 = 0, s2 = 0, s3 = 0;
            #pragma unroll
            for (int ky = 0; ky < 3; ky++) {
                int yy = y + ky - 1;
                if ((unsigned)yy <= 31u) {
                    const uint32_t* rp = (const uint32_t*)(B + c * 1024 + yy * 32);
                    uint32_t cur  = rp[wx];
                    uint32_t prev = wx ? rp[wx - 1] : 0u;
                    uint32_t nxt  = (wx < 7) ? rp[wx + 1] : 0u;
                    int wv = (int)DW1r[c * 3 + ky];
                    s0 = __dp4a((int)__byte_perm(cur, prev, 0x0107), wv, s0);
                    s1 = __dp4a((int)cur,                            wv, s1);
                    s2 = __dp4a((int)(cur >> 8),                     wv, s2);
                    s3 = __dp4a((int)__byte_perm(cur, nxt, 0x0432),  wv, s3);
                }
            }
            res[c][0] = clampi(rq2(s0), -8, 7);
            res[c][1] = clampi(rq2(s1), -8, 7);
            res[c][2] = clampi(rq2(s2), -8, 7);
            res[c][3] = clampi(rq2(s3), -8, 7);
        }
        uint4 o;
        o.x = pack4(res[0][0], res[1][0], res[2][0], 0);
        o.y = pack4(res[0][1], res[1][1], res[2][1], 0);
        o.z = pack4(res[0][2], res[1][2], res[2][2], 0);
        o.w = pack4(res[0][3], res[1][3], res[2][3], 0);
        int off = (wx * 4 + ((y >> 1) & 1) * 4) & 31;   // row rotation
        *(uint4*)(P1 + y * 32 + off) = o;
    }
    __syncthreads();

    // ---- pw1 (3->32) + relu + maxpool2 + act4 requant ----
    // Thread = (8 oc) x (4 pooled px). Rotated loads (conflict-free LDS.128).
    // D stored with bit-flip swizzle: word q -> q ^ ((q>>5&1)<<2).
    {
        int q   = tid & 63;
        int ocg = tid >> 6;
        int Y   = q >> 2;
        int X   = q & 3;
        int o0 = (8 * X + 4 * (Y & 1)) & 31;
        int o1 = (o0 + 4) & 31;
        const uint32_t* row0 = P1 + 64 * Y;
        const uint32_t* row1 = row0 + 32;
        uint4 A0 = *(const uint4*)(row0 + o0);
        uint4 A1 = *(const uint4*)(row0 + o1);
        uint4 B0 = *(const uint4*)(row1 + o0);
        uint4 B1 = *(const uint4*)(row1 + o1);
        int ta[8] = {(int)A0.x,(int)A0.y,(int)A0.z,(int)A0.w,
                     (int)A1.x,(int)A1.y,(int)A1.z,(int)A1.w};
        int tb[8] = {(int)B0.x,(int)B0.y,(int)B0.z,(int)B0.w,
                     (int)B1.x,(int)B1.y,(int)B1.z,(int)B1.w};
        uint32_t* Dw = (uint32_t*)D;
        int qs = q ^ (((q >> 5) & 1) << 2);   // bit-flip swizzle
        #pragma unroll
        for (int oo = 0; oo < 8; oo++) {
            int oc = ocg * 8 + oo;
            int wv = (int)PW1w[oc];
            int m[4];
            #pragma unroll
            for (int j = 0; j < 4; j++) {
                int s0 = __dp4a(ta[2*j],     wv, 0);
                int s1 = __dp4a(ta[2*j + 1], wv, 0);
                int s2 = __dp4a(tb[2*j],     wv, 0);
                int s3 = __dp4a(tb[2*j + 1], wv, 0);
                m[j] = max(max(max(s0, s1), max(s2, s3)), 0);
            }
            Dw[oc * 64 + qs] = fq4x4(pack4(m[0], m[1], m[2], m[3]));
        }
    }

    // ---- wait for prep kernel (PDL): first use of the large packed weights ----
    cudaGridDependencySynchronize();

    // ---- stage large packed weights (L2-hot), vectorized ----
    if (tid < 128) ((uint4*)PW2w)[tid] = ((const uint4*)gPW2)[tid];
    ((uint4*)PW3w)[tid]       = ((const uint4*)gPW3)[tid];
    ((uint4*)PW3w)[tid + 256] = ((const uint4*)gPW3)[tid + 256];
    if (tid < 96)  DW2r[tid] = gDW2r[tid];
    if (tid < 192) DW3r[tid] = gDW3r[tid];
    __syncthreads();

    // ---- dw2: depthwise 3x3, 32ch @16x16. Item = 8-px half-row of 1 ch.
    //      D loads use bit-flip swizzle; P2 stores use row-XOR swizzle. ----
    #pragma unroll
    for (int k = 0; k < 4; k++) {
        int item = tid + k * 256;          // 0..1023
        int c = item >> 5;
        int r = item & 31;
        int y = r >> 1, h = r & 1;
        const uint32_t* chb = (const uint32_t*)(D + c * 256);
        int acc[8] = {};
        #pragma unroll
        for (int ky = 0; ky < 3; ky++) {
            int yy = y + ky - 1;
            if ((unsigned)yy <= 15u) {
                int base = yy * 4;
                int xw = (yy & 8) >> 1;    // bit-flip swizzle
                uint32_t c0 = chb[(base + 2 * h) ^ xw];
                uint32_t c1 = chb[(base + 2 * h + 1) ^ xw];
                uint32_t lf = h ? chb[(base + 1) ^ xw] : 0u;
                uint32_t rt = h ? 0u : chb[(base + 2) ^ xw];
                int wv = (int)DW2r[c * 3 + ky];
                acc[0] = __dp4a((int)__byte_perm(c0, lf, 0x0107), wv, acc[0]);
                acc[1] = __dp4a((int)c0,                          wv, acc[1]);
                acc[2] = __dp4a((int)(c0 >> 8),                   wv, acc[2]);
                acc[3] = __dp4a((int)__byte_perm(c0, c1, 0x0432), wv, acc[3]);
                acc[4] = __dp4a((int)__byte_perm(c1, c0, 0x0107), wv, acc[4]);
                acc[5] = __dp4a((int)c1,                          wv, acc[5]);
                acc[6] = __dp4a((int)(c1 >> 8),                   wv, acc[6]);
                acc[7] = __dp4a((int)__byte_perm(c1, rt, 0x0432), wv, acc[7]);
            }
        }
        int g = c >> 2, ln = c & 3;
        int xmask = (((y >> 1) & 7) << 2) ^ ((g & 3) * 8);  // row-XOR + kgroup swizzle
        #pragma unroll
        for (int j = 0; j < 8; j++) {
            int xpix = h * 8 + j;
            int qidx = ((y >> 1) * 8 + (xpix >> 1)) * 4 + (y & 1) * 2 + (xpix & 1);
            ((signed char*)P2)[(g * 256 + (qidx ^ xmask)) * 4 + ln] =
                (signed char)clampi(rq2(acc[j]), -8, 7);
        }
    }
    __syncthreads();

    // ---- pw2 (32->64) via IMMA + relu + maxpool2 + requant ----
    // P2 read applies row-XOR swizzle; D3 store applies channel-XOR swizzle.
    {
        int w = tid >> 5, lane = tid & 31;
        int li4 = lane >> 2, lm4 = lane & 3;
        int m0 = (w & 3) * 16;
        int nh = w >> 2;
        int a0w = (int)PW2w[(m0 + li4) * 8 + lm4];
        int a1w = (int)PW2w[(m0 + li4 + 8) * 8 + lm4];
        int a2w = (int)PW2w[(m0 + li4) * 8 + 4 + lm4];
        int a3w = (int)PW2w[(m0 + li4 + 8) * 8 + 4 + lm4];
        int sw = lm4 * 8;
        #pragma unroll
        for (int t = 0; t < 16; t++) {
            int n0 = (nh * 16 + t) * 8;
            int nn = n0 + li4;
            int pxs = nn ^ (((nn >> 5) & 7) << 2) ^ sw;   // row-XOR swizzle
            int b0 = (int)P2[lm4 * 256 + pxs];
            int b1 = (int)P2[(4 + lm4) * 256 + pxs];
            int d0 = 0, d1 = 0, d2 = 0, d3 = 0;
            mma_s8(d0, d1, d2, d3, a0w, a1w, a2w, a3w, b0, b1);
            int mA = max(d0, d1);
            int mB = max(d2, d3);
            mA = max(mA, __shfl_xor_sync(0xffffffffu, mA, 1));
            mB = max(mB, __shfl_xor_sync(0xffffffffu, mB, 1));
            if (!(lane & 1)) {
                int q = n0 / 4 + (lm4 >> 1);
                int qs = ((((q >> 2) ^ li4) & 15) << 2) | (q & 3);  // chan-XOR swizzle
                D3[(m0 + li4) * 64 + qs]     = (signed char)fq4(mA);
                D3[(m0 + li4 + 8) * 64 + qs] = (signed char)fq4(mB);
            }
        }
    }
    __syncthreads();

    // ---- dw3: depthwise 3x3, 64ch @8x8. Item = full 8-px row of 1 ch.
    //      D3 loads apply channel-XOR swizzle. ----
    #pragma unroll
    for (int k = 0; k < 2; k++) {
        int item = tid + k * 256;          // 0..511
        int c = item >> 3;
        int y = item & 7;
        const uint32_t* chb = (const uint32_t*)D3 + c * 16;
        int xc = c & 7;                    // channel-XOR swizzle
        int acc[8] = {};
        #pragma unroll
        for (int ky = 0; ky < 3; ky++) {
            int yy = y + ky - 1;
            if ((unsigned)yy <= 7u) {
                uint32_t c0 = chb[(yy * 2) ^ xc];
                uint32_t c1 = chb[(yy * 2 + 1) ^ xc];
                int wv = (int)DW3r[c * 3 + ky];
                acc[0] = __dp4a((int)__byte_perm(c0, 0u, 0x0107), wv, acc[0]);
                acc[1] = __dp4a((int)c0,                          wv, acc[1]);
                acc[2] = __dp4a((int)(c0 >> 8),                   wv, acc[2]);
                acc[3] = __dp4a((int)__byte_perm(c0, c1, 0x0432), wv, acc[3]);
                acc[4] = __dp4a((int)__byte_perm(c1, c0, 0x0107), wv, acc[4]);
                acc[5] = __dp4a((int)c1,                          wv, acc[5]);
                acc[6] = __dp4a((int)(c1 >> 8),                   wv, acc[6]);
                acc[7] = __dp4a((int)__byte_perm(c1, 0u, 0x0432), wv, acc[7]);
            }
        }
        int g = c >> 2, ln = c & 3;
        int sw = (g & 3) * 8;
        #pragma unroll
        for (int j = 0; j < 8; j++) {
            int px = y * 8 + j;
            ((signed char*)P3)[(g * 64 + (px ^ sw)) * 4 + ln] =
                (signed char)clampi(rq2(acc[j]), -8, 7);
        }
    }
    __syncthreads();

    // ---- pw3 (64->128) via IMMA + global maxpool in registers -> Vb ----
    {
        int w = tid >> 5, lane = tid & 31;
        int li4 = lane >> 2, lm4 = lane & 3;
        int m0 = w * 16;
        int A[2][4];
        #pragma unroll
        for (int kt = 0; kt < 2; kt++) {
            A[kt][0] = (int)PW3w[(m0 + li4) * 16 + kt * 8 + lm4];
            A[kt][1] = (int)PW3w[(m0 + li4 + 8) * 16 + kt * 8 + lm4];
            A[kt][2] = (int)PW3w[(m0 + li4) * 16 + kt * 8 + 4 + lm4];
            A[kt][3] = (int)PW3w[(m0 + li4 + 8) * 16 + kt * 8 + 4 + lm4];
        }
        int sw = lm4 * 8;
        int mA = INT_MIN, mB = INT_MIN;
        #pragma unroll
        for (int t = 0; t < 8; t++) {
            int pxs = (t * 8 + li4) ^ sw;
            int d0 = 0, d1 = 0, d2 = 0, d3 = 0;
            #pragma unroll
            for (int kt = 0; kt < 2; kt++) {
                int b0 = (int)P3[(kt * 8 + lm4) * 64 + pxs];
                int b1 = (int)P3[(kt * 8 + 4 + lm4) * 64 + pxs];
                mma_s8(d0, d1, d2, d3, A[kt][0], A[kt][1], A[kt][2], A[kt][3], b0, b1);
            }
            mA = max(mA, max(d0, d1));
            mB = max(mB, max(d2, d3));
        }
        mA = max(mA, __shfl_xor_sync(0xffffffffu, mA, 1));
        mA = max(mA, __shfl_xor_sync(0xffffffffu, mA, 2));
        mB = max(mB, __shfl_xor_sync(0xffffffffu, mB, 1));
        mB = max(mB, __shfl_xor_sync(0xffffffffu, mB, 2));
        if (lm4 == 0) {
            Vb[m0 + li4]     = (unsigned char)fq4(mA);
            Vb[m0 + li4 + 8] = (unsigned char)fq4(mB);
        }
    }
    __syncthreads();

    // ---- fc1: 128->256 (weights streamed from global, coalesced, L2-hot) ----
    {
        const uint32_t* Vw = (const uint32_t*)Vb;
        int S = 0;
        #pragma unroll 8
        for (int g = 0; g < 32; g++)
            S = __dp4a((int)Vw[g], (int)gFC1[g * 256 + tid], S);
        V2b[tid] = (unsigned char)fq4(S);
    }
    __syncthreads();

    // ---- fc2: 256->10 with 10 oc x 8 lanes; output int8 quant (2S trick) ----
    if (tid < 80) {
        int oc = tid >> 3, l = tid & 7;
        const uint32_t* Vw = (const uint32_t*)V2b;
        int S = 0;
        #pragma unroll
        for (int k = 0; k < 8; k++) {
            int g = l + k * 8;
            S = __dp4a((int)Vw[g], (int)gFC2[oc * 64 + g], S);
        }
        #pragma unroll
        for (int off = 4; off; off >>= 1) S += __shfl_down_sync(0xffffffffu, S, off, 8);
        if (l == 0) {
            int o = clampi(2 * S, -128, 127);
            out[(size_t)b * 10 + oc] = (float)o * 0.0625f;
        }
    }
}

extern "C" void kernel_launch(void* const* d_in, const int* in_sizes, int n_in,
                              void* d_out, int out_size)
{
    (void)in_sizes; (void)n_in; (void)out_size;
    const float* x   = (const float*)d_in[0];
    const float* w0  = (const float*)d_in[1];
    const float* dw1 = (const float*)d_in[2];
    const float* pw1 = (const float*)d_in[3];
    const float* dw2 = (const float*)d_in[4];
    const float* pw2 = (const float*)d_in[5];
    const float* dw3 = (const float*)d_in[6];
    const float* pw3 = (const float*)d_in[7];
    const float* wc1 = (const float*)d_in[8];
    const float* wc2 = (const float*)d_in[9];
    float* out = (float*)d_out;

    prep_kernel<<<48, THREADS>>>(dw2, pw2, dw3, pw3, wc1, wc2);

    // qnet launched with Programmatic Stream Serialization: its CTAs begin
    // executing conv0/dw1/pw1 (per-CTA-quantized small weights) while prep
    // finishes; cudaGridDependencySynchronize() before dw2 orders the large
    // weight reads after prep's trigger.
    cudaLaunchConfig_t cfg = {};
    cfg.gridDim = dim3(1024, 1, 1);
    cfg.blockDim = dim3(THREADS, 1, 1);
    cfg.dynamicSmemBytes = SM_BYTES;
    cfg.stream = 0;
    cudaLaunchAttribute attrs[1];
    attrs[0].id = cudaLaunchAttributeProgrammaticStreamSerialization;
    attrs[0].val.programmaticStreamSerializationAllowed = 1;
    cfg.attrs = attrs;
    cfg.numAttrs = 1;
    cudaLaunchKernelEx(&cfg, qnet_kernel, x, out, w0, dw1, pw1);
}